// round 1
// baseline (speedup 1.0000x reference)
#include <cuda_runtime.h>
#include <cuda_bf16.h>
#include <cstdio>

// ---------------- problem constants ----------------
#define BB      1024
#define S_OUT   30
#define S_IN    17
#define D_INN   3
#define HH      4
#define DKQ_I   6
#define DV_I    8
#define HID_I   256
#define OUT_I   64
#define DKQ_O   64
#define DV_O    64
#define HID_O   1024
#define OUT_O   1080

#define NU      (BB * S_OUT)          // 30720 inner units
#define CTXI_PER_U (HH * S_IN * DV_I) // 544
#define FC1I_M  (NU * HH)             // 122880
#define FC1I_K  (S_IN * DV_I)         // 136

// ---------------- scratch (device globals; no runtime allocation) ----------------
__device__ float g_ctx  [(size_t)NU * CTXI_PER_U];   // [30720][4][136]
__device__ float g_h1   [(size_t)FC1I_M * HID_I];    // [122880][256] == [30720][1024]
__device__ float g_seq  [(size_t)NU * OUT_I];        // [30720][64]
__device__ float g_wpack[64 * 768];                  // packed outer qkv weights
__device__ float g_bpack[768];
__device__ float g_qkv  [(size_t)NU * 768];          // [30720][768]  (q|k|v, heads packed)
__device__ float g_ctxo [(size_t)BB * HH * S_OUT * DV_O]; // [4096][1920]
__device__ float g_h2   [(size_t)BB * HH * HID_O];   // [4096][1024] == [1024][4096]

// ---------------- inner attention: 1 block per (b,s_out), 1 warp per head ----------------
__global__ void inner_attn_kernel(const float* __restrict__ x,
                                  const float* __restrict__ iwq, const float* __restrict__ ibq,
                                  const float* __restrict__ iwk, const float* __restrict__ ibk,
                                  const float* __restrict__ iwv, const float* __restrict__ ibv)
{
    const int u    = blockIdx.x;
    const int tid  = threadIdx.x;
    const int h    = tid >> 5;
    const int lane = tid & 31;

    __shared__ float sx[S_IN * D_INN];
    __shared__ float sq[HH][S_IN][DKQ_I];
    __shared__ float sk[HH][S_IN][DKQ_I];
    __shared__ float sv[HH][S_IN][DV_I];
    __shared__ float ss[HH][S_IN][S_IN];

    const float* xp = x + (size_t)u * (S_IN * D_INN);
    if (tid < S_IN * D_INN) sx[tid] = xp[tid];
    __syncthreads();

    // q,k,v for this head: 17*(6+6+8)=340 outputs per warp
    for (int i = lane; i < S_IN * (2 * DKQ_I + DV_I); i += 32) {
        if (i < S_IN * DKQ_I) {
            int p = i / DKQ_I, c = i % DKQ_I;
            float s = ibq[h * DKQ_I + c];
            #pragma unroll
            for (int d = 0; d < D_INN; d++)
                s += sx[p * D_INN + d] * iwq[(h * D_INN + d) * DKQ_I + c];
            sq[h][p][c] = s;
        } else if (i < 2 * S_IN * DKQ_I) {
            int j = i - S_IN * DKQ_I;
            int p = j / DKQ_I, c = j % DKQ_I;
            float s = ibk[h * DKQ_I + c];
            #pragma unroll
            for (int d = 0; d < D_INN; d++)
                s += sx[p * D_INN + d] * iwk[(h * D_INN + d) * DKQ_I + c];
            sk[h][p][c] = s;
        } else {
            int j = i - 2 * S_IN * DKQ_I;
            int p = j / DV_I, c = j % DV_I;
            float s = ibv[h * DV_I + c];
            #pragma unroll
            for (int d = 0; d < D_INN; d++)
                s += sx[p * D_INN + d] * iwv[(h * D_INN + d) * DV_I + c];
            sv[h][p][c] = s;
        }
    }
    __syncwarp();

    const float scale = 0.40824829046386302f;   // 1/sqrt(6)
    for (int i = lane; i < S_IN * S_IN; i += 32) {
        int p = i / S_IN, j = i % S_IN;
        float s = 0.f;
        #pragma unroll
        for (int c = 0; c < DKQ_I; c++) s += sq[h][p][c] * sk[h][j][c];
        ss[h][p][j] = s * scale;
    }
    __syncwarp();

    if (lane < S_IN) {
        int p = lane;
        float m = -1e30f;
        #pragma unroll
        for (int j = 0; j < S_IN; j++) m = fmaxf(m, ss[h][p][j]);
        float sum = 0.f;
        #pragma unroll
        for (int j = 0; j < S_IN; j++) { float e = __expf(ss[h][p][j] - m); ss[h][p][j] = e; sum += e; }
        float inv = 1.f / sum;
        #pragma unroll
        for (int j = 0; j < S_IN; j++) ss[h][p][j] *= inv;
    }
    __syncwarp();

    float* op = g_ctx + (size_t)u * CTXI_PER_U + h * (S_IN * DV_I);
    for (int i = lane; i < S_IN * DV_I; i += 32) {
        int p = i / DV_I, c = i % DV_I;
        float s = 0.f;
        #pragma unroll
        for (int j = 0; j < S_IN; j++) s += ss[h][p][j] * sv[h][j][c];
        op[p * DV_I + c] = s;
    }
}

// ---------------- pack outer qkv weights to [64][768] ----------------
__global__ void pack_qkv_w(const float* __restrict__ owq, const float* __restrict__ owk,
                           const float* __restrict__ owv,
                           const float* __restrict__ obq, const float* __restrict__ obk,
                           const float* __restrict__ obv)
{
    int i = blockIdx.x * blockDim.x + threadIdx.x;
    if (i < 64 * 768) {
        int k = i / 768, col = i % 768;
        int sel = col >> 8;
        int hd  = col & 255;
        int h = hd >> 6, d = hd & 63;
        const float* w = (sel == 0) ? owq : (sel == 1) ? owk : owv;
        g_wpack[i] = w[(h * 64 + k) * 64 + d];
    }
    if (i < 768) {
        int sel = i >> 8, hd = i & 255;
        int h = hd >> 6, d = hd & 63;
        const float* b = (sel == 0) ? obq : (sel == 1) ? obk : obv;
        g_bpack[i] = b[h * 64 + d];
    }
}

// ---------------- outer attention: 1 block per (b,h) ----------------
__global__ void outer_attn_kernel()
{
    const int bh = blockIdx.x;         // b*4+h
    const int b  = bh >> 2, h = bh & 3;
    const int tid = threadIdx.x;       // 128

    __shared__ float sq[S_OUT][65], sk[S_OUT][65], sv[S_OUT][65];
    __shared__ float ss[S_OUT][S_OUT];

    for (int i = tid; i < S_OUT * 64; i += blockDim.x) {
        int p = i >> 6, d = i & 63;
        size_t base = (size_t)(b * S_OUT + p) * 768;
        sq[p][d] = g_qkv[base +        h * 64 + d];
        sk[p][d] = g_qkv[base + 256 +  h * 64 + d];
        sv[p][d] = g_qkv[base + 512 +  h * 64 + d];
    }
    __syncthreads();

    for (int i = tid; i < S_OUT * S_OUT; i += blockDim.x) {
        int p = i / S_OUT, j = i % S_OUT;
        float s = 0.f;
        #pragma unroll 16
        for (int c = 0; c < 64; c++) s += sq[p][c] * sk[j][c];
        ss[p][j] = s * 0.125f;          // 1/sqrt(64)
    }
    __syncthreads();

    if (tid < S_OUT) {
        int p = tid;
        float m = -1e30f;
        #pragma unroll
        for (int j = 0; j < S_OUT; j++) m = fmaxf(m, ss[p][j]);
        float sum = 0.f;
        #pragma unroll
        for (int j = 0; j < S_OUT; j++) { float e = __expf(ss[p][j] - m); ss[p][j] = e; sum += e; }
        float inv = 1.f / sum;
        #pragma unroll
        for (int j = 0; j < S_OUT; j++) ss[p][j] *= inv;
    }
    __syncthreads();

    float* op = g_ctxo + (size_t)bh * (S_OUT * 64);
    for (int i = tid; i < S_OUT * 64; i += blockDim.x) {
        int p = i >> 6, c = i & 63;
        float s = 0.f;
        #pragma unroll
        for (int j = 0; j < S_OUT; j++) s += ss[p][j] * sv[j][c];
        op[i] = s;
    }
}

// ---------------- generic fp32 GEMM: C = act(A[M,K] @ B[K,N] + bias) ----------------
// 64x64 tile, BK=16, 256 threads, 4x4 per-thread micro-tile, float4 smem reads.
template<int ACT>
__global__ void __launch_bounds__(256)
gemm_kernel(const float* __restrict__ A, const float* __restrict__ B,
            const float* __restrict__ bias, float* __restrict__ C,
            int M, int N, int K)
{
    __shared__ __align__(16) float As[16][68];   // [k][m], padded row (272B, 16B-aligned)
    __shared__ __align__(16) float Bs[16][64];   // [k][n]

    const int tid = threadIdx.x;
    const int tx = tid & 15, ty = tid >> 4;
    const int bm = blockIdx.y * 64, bn = blockIdx.x * 64;

    float acc[4][4] = {};

    for (int k0 = 0; k0 < K; k0 += 16) {
        {   // A tile 64x16: thread loads 4 consecutive k for one m-row
            int r = tid >> 2;
            int c = (tid & 3) * 4;
            int gm = bm + r;
            #pragma unroll
            for (int i = 0; i < 4; i++) {
                int gk = k0 + c + i;
                As[c + i][r] = (gm < M && gk < K) ? A[(size_t)gm * K + gk] : 0.f;
            }
        }
        {   // B tile 16x64: thread loads 4 consecutive n for one k-row
            int r = tid >> 4;
            int c = (tid & 15) * 4;
            int gk = k0 + r;
            #pragma unroll
            for (int i = 0; i < 4; i++) {
                int gn = bn + c + i;
                Bs[r][c + i] = (gk < K && gn < N) ? B[(size_t)gk * N + gn] : 0.f;
            }
        }
        __syncthreads();

        #pragma unroll
        for (int kk = 0; kk < 16; kk++) {
            float4 av = *reinterpret_cast<const float4*>(&As[kk][ty * 4]);
            float4 bv = *reinterpret_cast<const float4*>(&Bs[kk][tx * 4]);
            float a[4] = {av.x, av.y, av.z, av.w};
            float bb[4] = {bv.x, bv.y, bv.z, bv.w};
            #pragma unroll
            for (int i = 0; i < 4; i++)
                #pragma unroll
                for (int j = 0; j < 4; j++)
                    acc[i][j] += a[i] * bb[j];
        }
        __syncthreads();
    }

    #pragma unroll
    for (int i = 0; i < 4; i++) {
        int gm = bm + ty * 4 + i;
        if (gm >= M) continue;
        #pragma unroll
        for (int j = 0; j < 4; j++) {
            int gn = bn + tx * 4 + j;
            if (gn >= N) continue;
            float v = acc[i][j] + bias[gn];
            if (ACT) v = tanhf(v);
            C[(size_t)gm * N + gn] = v;
        }
    }
}

static inline int cdiv(int a, int b) { return (a + b - 1) / b; }

extern "C" void kernel_launch(void* const* d_in, const int* in_sizes, int n_in,
                              void* d_out, int out_size)
{
    (void)in_sizes; (void)n_in; (void)out_size;
    const float* x   = (const float*)d_in[0];
    const float* iwq = (const float*)d_in[1];
    const float* ibq = (const float*)d_in[2];
    const float* iwk = (const float*)d_in[3];
    const float* ibk = (const float*)d_in[4];
    const float* iwv = (const float*)d_in[5];
    const float* ibv = (const float*)d_in[6];
    const float* iw1 = (const float*)d_in[7];
    const float* ib1 = (const float*)d_in[8];
    const float* iw2 = (const float*)d_in[9];
    const float* ib2 = (const float*)d_in[10];
    const float* owq = (const float*)d_in[11];
    const float* obq = (const float*)d_in[12];
    const float* owk = (const float*)d_in[13];
    const float* obk = (const float*)d_in[14];
    const float* owv = (const float*)d_in[15];
    const float* obv = (const float*)d_in[16];
    const float* ow1 = (const float*)d_in[17];
    const float* ob1 = (const float*)d_in[18];
    const float* ow2 = (const float*)d_in[19];
    const float* ob2 = (const float*)d_in[20];
    float* out = (float*)d_out;

    // resolve scratch symbols
    float *p_ctx, *p_h1, *p_seq, *p_wpack, *p_bpack, *p_qkv, *p_ctxo, *p_h2;
    cudaGetSymbolAddress((void**)&p_ctx,   g_ctx);
    cudaGetSymbolAddress((void**)&p_h1,    g_h1);
    cudaGetSymbolAddress((void**)&p_seq,   g_seq);
    cudaGetSymbolAddress((void**)&p_wpack, g_wpack);
    cudaGetSymbolAddress((void**)&p_bpack, g_bpack);
    cudaGetSymbolAddress((void**)&p_qkv,   g_qkv);
    cudaGetSymbolAddress((void**)&p_ctxo,  g_ctxo);
    cudaGetSymbolAddress((void**)&p_h2,    g_h2);

    // 1) inner attention -> g_ctx [30720][544]
    inner_attn_kernel<<<NU, 128>>>(x, iwq, ibq, iwk, ibk, iwv, ibv);

    // 2) fc1_i: [122880,136] @ [136,256] + tanh -> g_h1
    gemm_kernel<1><<<dim3(cdiv(HID_I, 64), cdiv(FC1I_M, 64)), 256>>>(
        p_ctx, iw1, ib1, p_h1, FC1I_M, HID_I, FC1I_K);

    // 3) fc2_i: [30720,1024] @ [1024,64] -> g_seq
    gemm_kernel<0><<<dim3(cdiv(OUT_I, 64), cdiv(NU, 64)), 256>>>(
        p_h1, iw2, ib2, p_seq, NU, OUT_I, HH * HID_I);

    // 4) outer qkv: pack weights, then [30720,64] @ [64,768] -> g_qkv
    pack_qkv_w<<<cdiv(64 * 768, 256), 256>>>(owq, owk, owv, obq, obk, obv);
    gemm_kernel<0><<<dim3(cdiv(768, 64), cdiv(NU, 64)), 256>>>(
        p_seq, p_wpack, p_bpack, p_qkv, NU, 768, OUT_I);

    // 5) outer attention -> g_ctxo [4096][1920]
    outer_attn_kernel<<<BB * HH, 128>>>();

    // 6) fc1_o: [4096,1920] @ [1920,1024] + tanh -> g_h2
    gemm_kernel<1><<<dim3(cdiv(HID_O, 64), cdiv(BB * HH, 64)), 256>>>(
        p_ctxo, ow1, ob1, p_h2, BB * HH, HID_O, S_OUT * DV_O);

    // 7) fc2_o: [1024,4096] @ [4096,1080] -> out
    gemm_kernel<0><<<dim3(cdiv(OUT_O, 64), cdiv(BB, 64)), 256>>>(
        p_h2, ow2, ob2, out, BB, OUT_O, HH * HID_O);
}

// round 2
// speedup vs baseline: 1.2700x; 1.2700x over previous
#include <cuda_runtime.h>
#include <cuda_bf16.h>
#include <cstdint>

// ---------------- problem constants ----------------
#define BB      1024
#define S_OUT   30
#define S_IN    17
#define D_INN   3
#define HH      4
#define DKQ_I   6
#define DV_I    8
#define HID_I   256
#define OUT_I   64
#define DKQ_O   64
#define DV_O    64
#define HID_O   1024
#define OUT_O   1080

#define NU      (BB * S_OUT)          // 30720 inner units
#define CTXI_PER_U (HH * S_IN * DV_I) // 544
#define FC1I_M  (NU * HH)             // 122880
#define FC1I_K  (S_IN * DV_I)         // 136

// ---------------- scratch (device globals; no runtime allocation) ----------------
__device__ float g_ctx  [(size_t)NU * CTXI_PER_U];   // [30720][4][136]
__device__ float g_h1   [(size_t)FC1I_M * HID_I];    // [122880][256] == [30720][1024]
__device__ float g_seq  [(size_t)NU * OUT_I];        // [30720][64]
__device__ float g_wpack[64 * 768];                  // packed outer qkv weights
__device__ float g_bpack[768];
__device__ float g_qkv  [(size_t)NU * 768];          // [30720][768]  (q|k|v, heads packed)
__device__ float g_ctxo [(size_t)BB * HH * S_OUT * DV_O]; // [4096][1920]
__device__ float g_h2   [(size_t)BB * HH * HID_O];   // [4096][1024] == [1024][4096]

// ---------------- helpers ----------------
__device__ __forceinline__ uint32_t f2tf32(float f) {
    uint32_t u; asm("cvt.rna.tf32.f32 %0, %1;" : "=r"(u) : "f"(f)); return u;
}
__device__ __forceinline__ float tanh_fast(float x) {
    float y; asm("tanh.approx.f32 %0, %1;" : "=f"(y) : "f"(x)); return y;
}
__device__ __forceinline__ void mma_tf32(float c[4], const uint32_t a[4], const uint32_t b[2]) {
    asm volatile(
        "mma.sync.aligned.m16n8k8.row.col.f32.tf32.tf32.f32 "
        "{%0,%1,%2,%3}, {%4,%5,%6,%7}, {%8,%9}, {%0,%1,%2,%3};"
        : "+f"(c[0]), "+f"(c[1]), "+f"(c[2]), "+f"(c[3])
        : "r"(a[0]), "r"(a[1]), "r"(a[2]), "r"(a[3]), "r"(b[0]), "r"(b[1]));
}

// ---------------- inner attention: 1 block per (b,s_out), 1 warp per head ----------------
__global__ void inner_attn_kernel(const float* __restrict__ x,
                                  const float* __restrict__ iwq, const float* __restrict__ ibq,
                                  const float* __restrict__ iwk, const float* __restrict__ ibk,
                                  const float* __restrict__ iwv, const float* __restrict__ ibv)
{
    const int u    = blockIdx.x;
    const int tid  = threadIdx.x;
    const int h    = tid >> 5;
    const int lane = tid & 31;

    __shared__ float sx[S_IN * D_INN];
    __shared__ float sq[HH][S_IN][DKQ_I];
    __shared__ float sk[HH][S_IN][DKQ_I];
    __shared__ float sv[HH][S_IN][DV_I];
    __shared__ float ss[HH][S_IN][S_IN];

    const float* xp = x + (size_t)u * (S_IN * D_INN);
    if (tid < S_IN * D_INN) sx[tid] = xp[tid];
    __syncthreads();

    for (int i = lane; i < S_IN * (2 * DKQ_I + DV_I); i += 32) {
        if (i < S_IN * DKQ_I) {
            int p = i / DKQ_I, c = i % DKQ_I;
            float s = ibq[h * DKQ_I + c];
            #pragma unroll
            for (int d = 0; d < D_INN; d++)
                s += sx[p * D_INN + d] * iwq[(h * D_INN + d) * DKQ_I + c];
            sq[h][p][c] = s;
        } else if (i < 2 * S_IN * DKQ_I) {
            int j = i - S_IN * DKQ_I;
            int p = j / DKQ_I, c = j % DKQ_I;
            float s = ibk[h * DKQ_I + c];
            #pragma unroll
            for (int d = 0; d < D_INN; d++)
                s += sx[p * D_INN + d] * iwk[(h * D_INN + d) * DKQ_I + c];
            sk[h][p][c] = s;
        } else {
            int j = i - 2 * S_IN * DKQ_I;
            int p = j / DV_I, c = j % DV_I;
            float s = ibv[h * DV_I + c];
            #pragma unroll
            for (int d = 0; d < D_INN; d++)
                s += sx[p * D_INN + d] * iwv[(h * D_INN + d) * DV_I + c];
            sv[h][p][c] = s;
        }
    }
    __syncwarp();

    const float scale = 0.40824829046386302f;   // 1/sqrt(6)
    for (int i = lane; i < S_IN * S_IN; i += 32) {
        int p = i / S_IN, j = i % S_IN;
        float s = 0.f;
        #pragma unroll
        for (int c = 0; c < DKQ_I; c++) s += sq[h][p][c] * sk[h][j][c];
        ss[h][p][j] = s * scale;
    }
    __syncwarp();

    if (lane < S_IN) {
        int p = lane;
        float m = -1e30f;
        #pragma unroll
        for (int j = 0; j < S_IN; j++) m = fmaxf(m, ss[h][p][j]);
        float sum = 0.f;
        #pragma unroll
        for (int j = 0; j < S_IN; j++) { float e = __expf(ss[h][p][j] - m); ss[h][p][j] = e; sum += e; }
        float inv = 1.f / sum;
        #pragma unroll
        for (int j = 0; j < S_IN; j++) ss[h][p][j] *= inv;
    }
    __syncwarp();

    float* op = g_ctx + (size_t)u * CTXI_PER_U + h * (S_IN * DV_I);
    for (int i = lane; i < S_IN * DV_I; i += 32) {
        int p = i / DV_I, c = i % DV_I;
        float s = 0.f;
        #pragma unroll
        for (int j = 0; j < S_IN; j++) s += ss[h][p][j] * sv[h][j][c];
        op[p * DV_I + c] = s;
    }
}

// ---------------- pack outer qkv weights to [64][768] ----------------
__global__ void pack_qkv_w(const float* __restrict__ owq, const float* __restrict__ owk,
                           const float* __restrict__ owv,
                           const float* __restrict__ obq, const float* __restrict__ obk,
                           const float* __restrict__ obv)
{
    int i = blockIdx.x * blockDim.x + threadIdx.x;
    if (i < 64 * 768) {
        int k = i / 768, col = i % 768;
        int sel = col >> 8;
        int hd  = col & 255;
        int h = hd >> 6, d = hd & 63;
        const float* w = (sel == 0) ? owq : (sel == 1) ? owk : owv;
        g_wpack[i] = w[(h * 64 + k) * 64 + d];
    }
    if (i < 768) {
        int sel = i >> 8, hd = i & 255;
        int h = hd >> 6, d = hd & 63;
        const float* b = (sel == 0) ? obq : (sel == 1) ? obk : obv;
        g_bpack[i] = b[h * 64 + d];
    }
}

// ---------------- outer attention: 1 block per (b,h) ----------------
__global__ void outer_attn_kernel()
{
    const int bh = blockIdx.x;         // b*4+h
    const int b  = bh >> 2, h = bh & 3;
    const int tid = threadIdx.x;       // 128

    __shared__ float sq[S_OUT][65], sk[S_OUT][65], sv[S_OUT][65];
    __shared__ float ss[S_OUT][S_OUT];

    for (int i = tid; i < S_OUT * 64; i += blockDim.x) {
        int p = i >> 6, d = i & 63;
        size_t base = (size_t)(b * S_OUT + p) * 768;
        sq[p][d] = g_qkv[base +        h * 64 + d];
        sk[p][d] = g_qkv[base + 256 +  h * 64 + d];
        sv[p][d] = g_qkv[base + 512 +  h * 64 + d];
    }
    __syncthreads();

    for (int i = tid; i < S_OUT * S_OUT; i += blockDim.x) {
        int p = i / S_OUT, j = i % S_OUT;
        float s = 0.f;
        #pragma unroll 16
        for (int c = 0; c < 64; c++) s += sq[p][c] * sk[j][c];
        ss[p][j] = s * 0.125f;          // 1/sqrt(64)
    }
    __syncthreads();

    if (tid < S_OUT) {
        int p = tid;
        float m = -1e30f;
        #pragma unroll
        for (int j = 0; j < S_OUT; j++) m = fmaxf(m, ss[p][j]);
        float sum = 0.f;
        #pragma unroll
        for (int j = 0; j < S_OUT; j++) { float e = __expf(ss[p][j] - m); ss[p][j] = e; sum += e; }
        float inv = 1.f / sum;
        #pragma unroll
        for (int j = 0; j < S_OUT; j++) ss[p][j] *= inv;
    }
    __syncthreads();

    float* op = g_ctxo + (size_t)bh * (S_OUT * 64);
    for (int i = tid; i < S_OUT * 64; i += blockDim.x) {
        int p = i >> 6, c = i & 63;
        float s = 0.f;
        #pragma unroll
        for (int j = 0; j < S_OUT; j++) s += ss[p][j] * sv[j][c];
        op[i] = s;
    }
}

// ---------------- tf32 tensor-core GEMM: C = act(A[M,K] @ B[K,N] + bias) ----------------
// 128x64 block tile, BK=16, 256 threads (8 warps as 4m x 2n, 32x32 warp tile).
// M must be a multiple of 128 (true for all call sites). N, K arbitrary.
// Smem row strides are ==8 (mod 32) words -> conflict-free fragment loads.
template<int ACT>
__global__ void __launch_bounds__(256)
gemm_tf32_kernel(const float* __restrict__ A, const float* __restrict__ B,
                 const float* __restrict__ bias, float* __restrict__ C,
                 int M, int N, int K)
{
    __shared__ uint32_t As[16][136];   // [k][m], stride 136 % 32 == 8
    __shared__ uint32_t Bs[16][72];    // [k][n], stride 72  % 32 == 8

    const int tid  = threadIdx.x;
    const int warp = tid >> 5, lane = tid & 31;
    const int g = lane >> 2, t = lane & 3;           // groupID / tid-in-group
    const int bm = blockIdx.y * 128, bn = blockIdx.x * 64;
    const int wm = (warp >> 1) * 32;                 // warp m offset within tile
    const int wn = (warp & 1) * 32;                  // warp n offset within tile

    float acc[2][4][4] = {};

    for (int k0 = 0; k0 < K; k0 += 16) {
        {   // A tile 128x16: thread -> row tid>>1, k-chunk (tid&1)*8
            int r  = tid >> 1;
            int kb = (tid & 1) * 8;
            const float* ap = A + (size_t)(bm + r) * K;
            #pragma unroll
            for (int i = 0; i < 8; i++) {
                int gk = k0 + kb + i;
                float v = (gk < K) ? ap[gk] : 0.f;
                As[kb + i][r] = f2tf32(v);
            }
        }
        {   // B tile 16x64: thread -> row tid>>4, 4 consecutive n
            int r  = tid >> 4;
            int cb = (tid & 15) * 4;
            int gk = k0 + r;
            const float* bp = B + (size_t)gk * N;
            #pragma unroll
            for (int i = 0; i < 4; i++) {
                int gn = bn + cb + i;
                float v = (gk < K && gn < N) ? bp[gn] : 0.f;
                Bs[r][cb + i] = f2tf32(v);
            }
        }
        __syncthreads();

        #pragma unroll
        for (int ks = 0; ks < 16; ks += 8) {
            uint32_t af[2][4], bf[4][2];
            #pragma unroll
            for (int i = 0; i < 2; i++) {
                int m0 = wm + i * 16;
                af[i][0] = As[ks + t    ][m0 + g    ];
                af[i][1] = As[ks + t    ][m0 + g + 8];
                af[i][2] = As[ks + t + 4][m0 + g    ];
                af[i][3] = As[ks + t + 4][m0 + g + 8];
            }
            #pragma unroll
            for (int j = 0; j < 4; j++) {
                int n0 = wn + j * 8;
                bf[j][0] = Bs[ks + t    ][n0 + g];
                bf[j][1] = Bs[ks + t + 4][n0 + g];
            }
            #pragma unroll
            for (int i = 0; i < 2; i++)
                #pragma unroll
                for (int j = 0; j < 4; j++)
                    mma_tf32(acc[i][j], af[i], bf[j]);
        }
        __syncthreads();
    }

    // epilogue: c0=(g,2t) c1=(g,2t+1) c2=(g+8,2t) c3=(g+8,2t+1)
    #pragma unroll
    for (int i = 0; i < 2; i++) {
        #pragma unroll
        for (int j = 0; j < 4; j++) {
            int row0 = bm + wm + i * 16 + g;
            int col0 = bn + wn + j * 8 + 2 * t;
            #pragma unroll
            for (int e = 0; e < 4; e++) {
                int r = row0 + (e >> 1) * 8;
                int c = col0 + (e & 1);
                if (c < N) {
                    float v = acc[i][j][e] + bias[c];
                    if (ACT) v = tanh_fast(v);
                    C[(size_t)r * N + c] = v;
                }
            }
        }
    }
}

static inline int cdiv(int a, int b) { return (a + b - 1) / b; }

extern "C" void kernel_launch(void* const* d_in, const int* in_sizes, int n_in,
                              void* d_out, int out_size)
{
    (void)in_sizes; (void)n_in; (void)out_size;
    const float* x   = (const float*)d_in[0];
    const float* iwq = (const float*)d_in[1];
    const float* ibq = (const float*)d_in[2];
    const float* iwk = (const float*)d_in[3];
    const float* ibk = (const float*)d_in[4];
    const float* iwv = (const float*)d_in[5];
    const float* ibv = (const float*)d_in[6];
    const float* iw1 = (const float*)d_in[7];
    const float* ib1 = (const float*)d_in[8];
    const float* iw2 = (const float*)d_in[9];
    const float* ib2 = (const float*)d_in[10];
    const float* owq = (const float*)d_in[11];
    const float* obq = (const float*)d_in[12];
    const float* owk = (const float*)d_in[13];
    const float* obk = (const float*)d_in[14];
    const float* owv = (const float*)d_in[15];
    const float* obv = (const float*)d_in[16];
    const float* ow1 = (const float*)d_in[17];
    const float* ob1 = (const float*)d_in[18];
    const float* ow2 = (const float*)d_in[19];
    const float* ob2 = (const float*)d_in[20];
    float* out = (float*)d_out;

    float *p_ctx, *p_h1, *p_seq, *p_wpack, *p_bpack, *p_qkv, *p_ctxo, *p_h2;
    cudaGetSymbolAddress((void**)&p_ctx,   g_ctx);
    cudaGetSymbolAddress((void**)&p_h1,    g_h1);
    cudaGetSymbolAddress((void**)&p_seq,   g_seq);
    cudaGetSymbolAddress((void**)&p_wpack, g_wpack);
    cudaGetSymbolAddress((void**)&p_bpack, g_bpack);
    cudaGetSymbolAddress((void**)&p_qkv,   g_qkv);
    cudaGetSymbolAddress((void**)&p_ctxo,  g_ctxo);
    cudaGetSymbolAddress((void**)&p_h2,    g_h2);

    // 1) inner attention -> g_ctx [30720][544]
    inner_attn_kernel<<<NU, 128>>>(x, iwq, ibq, iwk, ibk, iwv, ibv);

    // 2) fc1_i: [122880,136] @ [136,256] + tanh -> g_h1
    gemm_tf32_kernel<1><<<dim3(cdiv(HID_I, 64), FC1I_M / 128), 256>>>(
        p_ctx, iw1, ib1, p_h1, FC1I_M, HID_I, FC1I_K);

    // 3) fc2_i: [30720,1024] @ [1024,64] -> g_seq
    gemm_tf32_kernel<0><<<dim3(cdiv(OUT_I, 64), NU / 128), 256>>>(
        p_h1, iw2, ib2, p_seq, NU, OUT_I, HH * HID_I);

    // 4) outer qkv: pack weights, then [30720,64] @ [64,768] -> g_qkv
    pack_qkv_w<<<cdiv(64 * 768, 256), 256>>>(owq, owk, owv, obq, obk, obv);
    gemm_tf32_kernel<0><<<dim3(cdiv(768, 64), NU / 128), 256>>>(
        p_seq, p_wpack, p_bpack, p_qkv, NU, 768, OUT_I);

    // 5) outer attention -> g_ctxo [4096][1920]
    outer_attn_kernel<<<BB * HH, 128>>>();

    // 6) fc1_o: [4096,1920] @ [1920,1024] + tanh -> g_h2
    gemm_tf32_kernel<1><<<dim3(cdiv(HID_O, 64), (BB * HH) / 128), 256>>>(
        p_ctxo, ow1, ob1, p_h2, BB * HH, HID_O, S_OUT * DV_O);

    // 7) fc2_o: [1024,4096] @ [4096,1080] -> out
    gemm_tf32_kernel<0><<<dim3(cdiv(OUT_O, 64), BB / 128), 256>>>(
        p_h2, ow2, ob2, out, BB, OUT_O, HH * HID_O);
}

// round 3
// speedup vs baseline: 2.1368x; 1.6825x over previous
#include <cuda_runtime.h>
#include <cuda_bf16.h>
#include <cstdint>

// ---------------- problem constants ----------------
#define BB      1024
#define S_OUT   30
#define S_IN    17
#define D_INN   3
#define HH      4
#define DKQ_I   6
#define DV_I    8
#define HID_I   256
#define OUT_I   64
#define DKQ_O   64
#define DV_O    64
#define HID_O   1024
#define OUT_O   1080

#define NU      (BB * S_OUT)          // 30720 inner units
#define CTXI_PER_U (HH * S_IN * DV_I) // 544
#define FC1I_M  (NU * HH)             // 122880
#define FC1I_K  (S_IN * DV_I)         // 136

// ---------------- scratch (device globals; no runtime allocation) ----------------
__device__ float g_ctx  [(size_t)NU * CTXI_PER_U + 64]; // [30720][4][136] (+pad for f4 tail)
__device__ float g_h1   [(size_t)FC1I_M * HID_I];    // [122880][256] == [30720][1024]
__device__ float g_seq  [(size_t)NU * OUT_I];        // [30720][64]
__device__ float g_wpack[64 * 768];                  // packed outer qkv weights
__device__ float g_bpack[768];
__device__ float g_qkv  [(size_t)NU * 768];          // [30720][768]  (q|k|v, heads packed)
__device__ float g_ctxo [(size_t)BB * HH * S_OUT * DV_O]; // [4096][1920]
__device__ float g_h2   [(size_t)BB * HH * HID_O];   // [4096][1024] == [1024][4096]

// ---------------- helpers ----------------
__device__ __forceinline__ uint32_t f2tf32(float f) {
    uint32_t u; asm("cvt.rna.tf32.f32 %0, %1;" : "=r"(u) : "f"(f)); return u;
}
__device__ __forceinline__ float tanh_fast(float x) {
    float y; asm("tanh.approx.f32 %0, %1;" : "=f"(y) : "f"(x)); return y;
}
__device__ __forceinline__ void mma_tf32(float c[4], const uint32_t a[4], const uint32_t b[2]) {
    asm volatile(
        "mma.sync.aligned.m16n8k8.row.col.f32.tf32.tf32.f32 "
        "{%0,%1,%2,%3}, {%4,%5,%6,%7}, {%8,%9}, {%0,%1,%2,%3};"
        : "+f"(c[0]), "+f"(c[1]), "+f"(c[2]), "+f"(c[3])
        : "r"(a[0]), "r"(a[1]), "r"(a[2]), "r"(a[3]), "r"(b[0]), "r"(b[1]));
}

// ---------------- inner attention: 1 block per (b,s_out), 1 warp per head ----------------
__global__ void inner_attn_kernel(const float* __restrict__ x,
                                  const float* __restrict__ iwq, const float* __restrict__ ibq,
                                  const float* __restrict__ iwk, const float* __restrict__ ibk,
                                  const float* __restrict__ iwv, const float* __restrict__ ibv)
{
    const int u    = blockIdx.x;
    const int tid  = threadIdx.x;
    const int h    = tid >> 5;
    const int lane = tid & 31;

    __shared__ float sx[S_IN * D_INN];
    __shared__ float sq[HH][S_IN][DKQ_I];
    __shared__ float sk[HH][S_IN][DKQ_I];
    __shared__ float sv[HH][S_IN][DV_I];
    __shared__ float ss[HH][S_IN][S_IN];

    const float* xp = x + (size_t)u * (S_IN * D_INN);
    if (tid < S_IN * D_INN) sx[tid] = xp[tid];
    __syncthreads();

    for (int i = lane; i < S_IN * (2 * DKQ_I + DV_I); i += 32) {
        if (i < S_IN * DKQ_I) {
            int p = i / DKQ_I, c = i % DKQ_I;
            float s = ibq[h * DKQ_I + c];
            #pragma unroll
            for (int d = 0; d < D_INN; d++)
                s += sx[p * D_INN + d] * iwq[(h * D_INN + d) * DKQ_I + c];
            sq[h][p][c] = s;
        } else if (i < 2 * S_IN * DKQ_I) {
            int j = i - S_IN * DKQ_I;
            int p = j / DKQ_I, c = j % DKQ_I;
            float s = ibk[h * DKQ_I + c];
            #pragma unroll
            for (int d = 0; d < D_INN; d++)
                s += sx[p * D_INN + d] * iwk[(h * D_INN + d) * DKQ_I + c];
            sk[h][p][c] = s;
        } else {
            int j = i - 2 * S_IN * DKQ_I;
            int p = j / DV_I, c = j % DV_I;
            float s = ibv[h * DV_I + c];
            #pragma unroll
            for (int d = 0; d < D_INN; d++)
                s += sx[p * D_INN + d] * iwv[(h * D_INN + d) * DV_I + c];
            sv[h][p][c] = s;
        }
    }
    __syncwarp();

    const float scale = 0.40824829046386302f;   // 1/sqrt(6)
    for (int i = lane; i < S_IN * S_IN; i += 32) {
        int p = i / S_IN, j = i % S_IN;
        float s = 0.f;
        #pragma unroll
        for (int c = 0; c < DKQ_I; c++) s += sq[h][p][c] * sk[h][j][c];
        ss[h][p][j] = s * scale;
    }
    __syncwarp();

    if (lane < S_IN) {
        int p = lane;
        float m = -1e30f;
        #pragma unroll
        for (int j = 0; j < S_IN; j++) m = fmaxf(m, ss[h][p][j]);
        float sum = 0.f;
        #pragma unroll
        for (int j = 0; j < S_IN; j++) { float e = __expf(ss[h][p][j] - m); ss[h][p][j] = e; sum += e; }
        float inv = 1.f / sum;
        #pragma unroll
        for (int j = 0; j < S_IN; j++) ss[h][p][j] *= inv;
    }
    __syncwarp();

    float* op = g_ctx + (size_t)u * CTXI_PER_U + h * (S_IN * DV_I);
    for (int i = lane; i < S_IN * DV_I; i += 32) {
        int p = i / DV_I, c = i % DV_I;
        float s = 0.f;
        #pragma unroll
        for (int j = 0; j < S_IN; j++) s += ss[h][p][j] * sv[h][j][c];
        op[p * DV_I + c] = s;
    }
}

// ---------------- pack outer qkv weights (split so GEMM lands in ncu slot) ----
__global__ void pack_qkv_w(const float* __restrict__ owq, const float* __restrict__ owk,
                           const float* __restrict__ owv)
{
    int i = blockIdx.x * blockDim.x + threadIdx.x;
    if (i < 64 * 768) {
        int k = i / 768, col = i % 768;
        int sel = col >> 8;
        int hd  = col & 255;
        int h = hd >> 6, d = hd & 63;
        const float* w = (sel == 0) ? owq : (sel == 1) ? owk : owv;
        g_wpack[i] = w[(h * 64 + k) * 64 + d];
    }
}
__global__ void pack_qkv_b(const float* __restrict__ obq, const float* __restrict__ obk,
                           const float* __restrict__ obv)
{
    int i = blockIdx.x * blockDim.x + threadIdx.x;
    if (i < 768) {
        int sel = i >> 8, hd = i & 255;
        int h = hd >> 6, d = hd & 63;
        const float* b = (sel == 0) ? obq : (sel == 1) ? obk : obv;
        g_bpack[i] = b[h * 64 + d];
    }
}

// ---------------- outer attention: 1 block per (b,h) ----------------
__global__ void outer_attn_kernel()
{
    const int bh = blockIdx.x;         // b*4+h
    const int b  = bh >> 2, h = bh & 3;
    const int tid = threadIdx.x;       // 128

    __shared__ float sq[S_OUT][65], sk[S_OUT][65], sv[S_OUT][65];
    __shared__ float ss[S_OUT][S_OUT];

    for (int i = tid; i < S_OUT * 64; i += blockDim.x) {
        int p = i >> 6, d = i & 63;
        size_t base = (size_t)(b * S_OUT + p) * 768;
        sq[p][d] = g_qkv[base +        h * 64 + d];
        sk[p][d] = g_qkv[base + 256 +  h * 64 + d];
        sv[p][d] = g_qkv[base + 512 +  h * 64 + d];
    }
    __syncthreads();

    for (int i = tid; i < S_OUT * S_OUT; i += blockDim.x) {
        int p = i / S_OUT, j = i % S_OUT;
        float s = 0.f;
        #pragma unroll 16
        for (int c = 0; c < 64; c++) s += sq[p][c] * sk[j][c];
        ss[p][j] = s * 0.125f;          // 1/sqrt(64)
    }
    __syncthreads();

    if (tid < S_OUT) {
        int p = tid;
        float m = -1e30f;
        #pragma unroll
        for (int j = 0; j < S_OUT; j++) m = fmaxf(m, ss[p][j]);
        float sum = 0.f;
        #pragma unroll
        for (int j = 0; j < S_OUT; j++) { float e = __expf(ss[p][j] - m); ss[p][j] = e; sum += e; }
        float inv = 1.f / sum;
        #pragma unroll
        for (int j = 0; j < S_OUT; j++) ss[p][j] *= inv;
    }
    __syncthreads();

    float* op = g_ctxo + (size_t)bh * (S_OUT * 64);
    for (int i = tid; i < S_OUT * 64; i += blockDim.x) {
        int p = i >> 6, c = i & 63;
        float s = 0.f;
        #pragma unroll
        for (int j = 0; j < S_OUT; j++) s += ss[p][j] * sv[j][c];
        op[i] = s;
    }
}

// ---------------- tf32 tensor-core GEMM: C = act(A[M,K] @ B[K,N] + bias) ----------------
// 128x64 tile, BK=16, 256 threads (8 warps: 4m x 2n, 32x32 warp tile).
// Coalesced float4 global loads, register-prefetch pipeline, conflict-free smem.
// M % 128 == 0, K % 4 == 0, N % 4 == 0 at all call sites.
template<int ACT>
__global__ void __launch_bounds__(256)
gemm_tf32_kernel(const float* __restrict__ A, const float* __restrict__ B,
                 const float* __restrict__ bias, float* __restrict__ C,
                 int M, int N, int K)
{
    __shared__ uint32_t As[128][20];   // [m][k], stride 20: frag addr 20g+t covers all banks
    __shared__ uint32_t Bs[16][72];    // [k][n], stride 72: frag addr 8t+g covers all banks

    const int tid  = threadIdx.x;
    const int warp = tid >> 5, lane = tid & 31;
    const int g = lane >> 2, t = lane & 3;
    const int bm = blockIdx.y * 128, bn = blockIdx.x * 64;
    const int wm = (warp >> 1) * 32, wn = (warp & 1) * 32;

    // A: 512 float4 per tile; thread handles f4 ids {tid, tid+256}
    const int ar0 = tid >> 2;               // rows 0..63
    const int ac  = (tid & 3) * 4;          // k offset 0,4,8,12
    const int ar1 = ar0 + 64;               // rows 64..127
    // B: 256 float4; thread handles one: row tid>>4, n offset (tid&15)*4
    const int br = tid >> 4, bc = (tid & 15) * 4;

    float4 ra0, ra1, rb;

    auto fetch = [&](int k0) {
        // A row ar0/ar1, k = k0+ac .. +3
        {
            int gk = k0 + ac;
            const float* p0 = A + (size_t)(bm + ar0) * K + gk;
            const float* p1 = A + (size_t)(bm + ar1) * K + gk;
            if (gk + 3 < K) {
                ra0 = *reinterpret_cast<const float4*>(p0);
                ra1 = *reinterpret_cast<const float4*>(p1);
            } else {
                ra0.x = (gk+0<K)?p0[0]:0.f; ra0.y = (gk+1<K)?p0[1]:0.f;
                ra0.z = (gk+2<K)?p0[2]:0.f; ra0.w = (gk+3<K)?p0[3]:0.f;
                ra1.x = (gk+0<K)?p1[0]:0.f; ra1.y = (gk+1<K)?p1[1]:0.f;
                ra1.z = (gk+2<K)?p1[2]:0.f; ra1.w = (gk+3<K)?p1[3]:0.f;
            }
        }
        {
            int gk = k0 + br, gn = bn + bc;
            if (gk < K && gn < N)
                rb = *reinterpret_cast<const float4*>(B + (size_t)gk * N + gn);
            else
                rb = make_float4(0.f, 0.f, 0.f, 0.f);
        }
    };
    auto commit = [&]() {
        uint4 u0, u1, ub;
        u0.x = f2tf32(ra0.x); u0.y = f2tf32(ra0.y); u0.z = f2tf32(ra0.z); u0.w = f2tf32(ra0.w);
        u1.x = f2tf32(ra1.x); u1.y = f2tf32(ra1.y); u1.z = f2tf32(ra1.z); u1.w = f2tf32(ra1.w);
        ub.x = f2tf32(rb.x);  ub.y = f2tf32(rb.y);  ub.z = f2tf32(rb.z);  ub.w = f2tf32(rb.w);
        *reinterpret_cast<uint4*>(&As[ar0][ac]) = u0;
        *reinterpret_cast<uint4*>(&As[ar1][ac]) = u1;
        *reinterpret_cast<uint4*>(&Bs[br][bc])  = ub;
    };

    float acc[2][4][4] = {};

    fetch(0);
    for (int k0 = 0; k0 < K; k0 += 16) {
        commit();
        __syncthreads();
        if (k0 + 16 < K) fetch(k0 + 16);   // prefetch next tile while MMAs run

        #pragma unroll
        for (int ks = 0; ks < 16; ks += 8) {
            uint32_t af[2][4], bf[4][2];
            #pragma unroll
            for (int i = 0; i < 2; i++) {
                int m0 = wm + i * 16;
                af[i][0] = As[m0 + g    ][ks + t    ];
                af[i][1] = As[m0 + g + 8][ks + t    ];
                af[i][2] = As[m0 + g    ][ks + t + 4];
                af[i][3] = As[m0 + g + 8][ks + t + 4];
            }
            #pragma unroll
            for (int j = 0; j < 4; j++) {
                int n0 = wn + j * 8;
                bf[j][0] = Bs[ks + t    ][n0 + g];
                bf[j][1] = Bs[ks + t + 4][n0 + g];
            }
            #pragma unroll
            for (int i = 0; i < 2; i++)
                #pragma unroll
                for (int j = 0; j < 4; j++)
                    mma_tf32(acc[i][j], af[i], bf[j]);
        }
        __syncthreads();
    }

    // epilogue: c0=(g,2t) c1=(g,2t+1) c2=(g+8,2t) c3=(g+8,2t+1)
    #pragma unroll
    for (int i = 0; i < 2; i++) {
        #pragma unroll
        for (int j = 0; j < 4; j++) {
            int row0 = bm + wm + i * 16 + g;
            int col0 = bn + wn + j * 8 + 2 * t;
            #pragma unroll
            for (int e = 0; e < 4; e++) {
                int r = row0 + (e >> 1) * 8;
                int c = col0 + (e & 1);
                if (c < N) {
                    float v = acc[i][j][e] + bias[c];
                    if (ACT) v = tanh_fast(v);
                    C[(size_t)r * N + c] = v;
                }
            }
        }
    }
}

static inline int cdiv(int a, int b) { return (a + b - 1) / b; }

extern "C" void kernel_launch(void* const* d_in, const int* in_sizes, int n_in,
                              void* d_out, int out_size)
{
    (void)in_sizes; (void)n_in; (void)out_size;
    const float* x   = (const float*)d_in[0];
    const float* iwq = (const float*)d_in[1];
    const float* ibq = (const float*)d_in[2];
    const float* iwk = (const float*)d_in[3];
    const float* ibk = (const float*)d_in[4];
    const float* iwv = (const float*)d_in[5];
    const float* ibv = (const float*)d_in[6];
    const float* iw1 = (const float*)d_in[7];
    const float* ib1 = (const float*)d_in[8];
    const float* iw2 = (const float*)d_in[9];
    const float* ib2 = (const float*)d_in[10];
    const float* owq = (const float*)d_in[11];
    const float* obq = (const float*)d_in[12];
    const float* owk = (const float*)d_in[13];
    const float* obk = (const float*)d_in[14];
    const float* owv = (const float*)d_in[15];
    const float* obv = (const float*)d_in[16];
    const float* ow1 = (const float*)d_in[17];
    const float* ob1 = (const float*)d_in[18];
    const float* ow2 = (const float*)d_in[19];
    const float* ob2 = (const float*)d_in[20];
    float* out = (float*)d_out;

    float *p_ctx, *p_h1, *p_seq, *p_wpack, *p_bpack, *p_qkv, *p_ctxo, *p_h2;
    cudaGetSymbolAddress((void**)&p_ctx,   g_ctx);
    cudaGetSymbolAddress((void**)&p_h1,    g_h1);
    cudaGetSymbolAddress((void**)&p_seq,   g_seq);
    cudaGetSymbolAddress((void**)&p_wpack, g_wpack);
    cudaGetSymbolAddress((void**)&p_bpack, g_bpack);
    cudaGetSymbolAddress((void**)&p_qkv,   g_qkv);
    cudaGetSymbolAddress((void**)&p_ctxo,  g_ctxo);
    cudaGetSymbolAddress((void**)&p_h2,    g_h2);

    // launch order chosen so fc1_i (big GEMM) sits at index 3 = ncu capture slot
    // 0) inner attention -> g_ctx [30720][544]
    inner_attn_kernel<<<NU, 128>>>(x, iwq, ibq, iwk, ibk, iwv, ibv);

    // 1,2) pack outer qkv weights/bias (independent of inner)
    pack_qkv_w<<<cdiv(64 * 768, 256), 256>>>(owq, owk, owv);
    pack_qkv_b<<<cdiv(768, 256), 256>>>(obq, obk, obv);

    // 3) fc1_i: [122880,136] @ [136,256] + tanh -> g_h1
    gemm_tf32_kernel<1><<<dim3(cdiv(HID_I, 64), FC1I_M / 128), 256>>>(
        p_ctx, iw1, ib1, p_h1, FC1I_M, HID_I, FC1I_K);

    // 4) fc2_i: [30720,1024] @ [1024,64] -> g_seq
    gemm_tf32_kernel<0><<<dim3(cdiv(OUT_I, 64), NU / 128), 256>>>(
        p_h1, iw2, ib2, p_seq, NU, OUT_I, HH * HID_I);

    // 5) outer qkv: [30720,64] @ [64,768] -> g_qkv
    gemm_tf32_kernel<0><<<dim3(cdiv(768, 64), NU / 128), 256>>>(
        p_seq, p_wpack, p_bpack, p_qkv, NU, 768, OUT_I);

    // 6) outer attention -> g_ctxo [4096][1920]
    outer_attn_kernel<<<BB * HH, 128>>>();

    // 7) fc1_o: [4096,1920] @ [1920,1024] + tanh -> g_h2
    gemm_tf32_kernel<1><<<dim3(cdiv(HID_O, 64), (BB * HH) / 128), 256>>>(
        p_ctxo, ow1, ob1, p_h2, BB * HH, HID_O, S_OUT * DV_O);

    // 8) fc2_o: [1024,4096] @ [4096,1080] -> out
    gemm_tf32_kernel<0><<<dim3(cdiv(OUT_O, 64), BB / 128), 256>>>(
        p_h2, ow2, ob2, out, BB, OUT_O, HH * HID_O);
}

// round 5
// speedup vs baseline: 2.4541x; 1.1485x over previous
#include <cuda_runtime.h>
#include <cuda_bf16.h>
#include <cstdint>

// ---------------- problem constants ----------------
#define BB      1024
#define S_OUT   30
#define S_IN    17
#define D_INN   3
#define HH      4
#define DKQ_I   6
#define DV_I    8
#define HID_I   256
#define OUT_I   64
#define HID_O   1024
#define OUT_O   1080

#define NU      (BB * S_OUT)          // 30720 inner units
#define CTXI_PER_U (HH * S_IN * DV_I) // 544
#define FC1I_M  (NU * HH)             // 122880
#define FC1I_K  (S_IN * DV_I)         // 136

// ---------------- scratch (device globals; no runtime allocation) -------------
__device__ float g_ctx  [(size_t)NU * CTXI_PER_U + 64];   // [122880][136]
__device__ float g_h1   [(size_t)FC1I_M * HID_I];         // [30720][1024]
__device__ float g_seq  [(size_t)NU * 64];                // [30720][64]
__device__ float g_wpackT[768 * 64];                      // [n=768][k=64] rounded
__device__ float g_bpack[768];
__device__ float g_qkv  [(size_t)NU * 768];               // [30720][768]
__device__ float g_ctxo [(size_t)BB * HH * S_OUT * 64];   // [4096][1920]
__device__ float g_h2   [(size_t)BB * HH * HID_O];        // [1024][4096]
// transposed + tf32-rounded weights ([N][K])
__device__ float g_w1t[256 * 136];
__device__ float g_w2t[64 * 1024];
__device__ float g_w3t[1024 * 1920];
__device__ float g_w4t[1080 * 4096];

// ---------------- helpers ----------------
__device__ __forceinline__ float tanh_fast(float x) {
    float y; asm("tanh.approx.f32 %0, %1;" : "=f"(y) : "f"(x)); return y;
}
// round fp32 -> tf32 precision (RNA when followed by HW truncation of low 13 bits)
__device__ __forceinline__ float rnd_tf32(float f) {
    return __uint_as_float(__float_as_uint(f) + 0x1000u);
}
__device__ __forceinline__ uint32_t smem_u32(const void* p) {
    uint32_t a;
    asm("{ .reg .u64 t; cvta.to.shared.u64 t, %1; cvt.u32.u64 %0, t; }" : "=r"(a) : "l"(p));
    return a;
}
__device__ __forceinline__ void cp16(uint32_t dst, const void* src, int sz) {
    asm volatile("cp.async.cg.shared.global [%0], [%1], 16, %2;"
                 :: "r"(dst), "l"(src), "r"(sz) : "memory");
}
__device__ __forceinline__ void cp_commit() {
    asm volatile("cp.async.commit_group;" ::: "memory");
}
template<int N> __device__ __forceinline__ void cp_wait() {
    asm volatile("cp.async.wait_group %0;" :: "n"(N) : "memory");
}
__device__ __forceinline__ void mma_tf32(float c[4], uint32_t a0, uint32_t a1,
                                         uint32_t a2, uint32_t a3,
                                         uint32_t b0, uint32_t b1) {
    asm volatile(
        "mma.sync.aligned.m16n8k8.row.col.f32.tf32.tf32.f32 "
        "{%0,%1,%2,%3}, {%4,%5,%6,%7}, {%8,%9}, {%0,%1,%2,%3};"
        : "+f"(c[0]), "+f"(c[1]), "+f"(c[2]), "+f"(c[3])
        : "r"(a0), "r"(a1), "r"(a2), "r"(a3), "r"(b0), "r"(b1));
}

// ---------------- inner attention: 1 block per (b,s_out), 1 warp per head -----
__global__ void inner_attn_kernel(const float* __restrict__ x,
                                  const float* __restrict__ iwq, const float* __restrict__ ibq,
                                  const float* __restrict__ iwk, const float* __restrict__ ibk,
                                  const float* __restrict__ iwv, const float* __restrict__ ibv)
{
    const int u    = blockIdx.x;
    const int tid  = threadIdx.x;
    const int h    = tid >> 5;
    const int lane = tid & 31;

    __shared__ float sx[S_IN * D_INN];
    __shared__ float sq[HH][S_IN][DKQ_I];
    __shared__ float sk[HH][S_IN][DKQ_I];
    __shared__ float sv[HH][S_IN][DV_I];
    __shared__ float ss[HH][S_IN][S_IN];

    const float* xp = x + (size_t)u * (S_IN * D_INN);
    if (tid < S_IN * D_INN) sx[tid] = xp[tid];
    __syncthreads();

    for (int i = lane; i < S_IN * (2 * DKQ_I + DV_I); i += 32) {
        if (i < S_IN * DKQ_I) {
            int p = i / DKQ_I, c = i % DKQ_I;
            float s = ibq[h * DKQ_I + c];
            #pragma unroll
            for (int d = 0; d < D_INN; d++)
                s += sx[p * D_INN + d] * iwq[(h * D_INN + d) * DKQ_I + c];
            sq[h][p][c] = s;
        } else if (i < 2 * S_IN * DKQ_I) {
            int j = i - S_IN * DKQ_I;
            int p = j / DKQ_I, c = j % DKQ_I;
            float s = ibk[h * DKQ_I + c];
            #pragma unroll
            for (int d = 0; d < D_INN; d++)
                s += sx[p * D_INN + d] * iwk[(h * D_INN + d) * DKQ_I + c];
            sk[h][p][c] = s;
        } else {
            int j = i - 2 * S_IN * DKQ_I;
            int p = j / DV_I, c = j % DV_I;
            float s = ibv[h * DV_I + c];
            #pragma unroll
            for (int d = 0; d < D_INN; d++)
                s += sx[p * D_INN + d] * iwv[(h * D_INN + d) * DV_I + c];
            sv[h][p][c] = s;
        }
    }
    __syncwarp();

    const float scale = 0.40824829046386302f;   // 1/sqrt(6)
    for (int i = lane; i < S_IN * S_IN; i += 32) {
        int p = i / S_IN, j = i % S_IN;
        float s = 0.f;
        #pragma unroll
        for (int c = 0; c < DKQ_I; c++) s += sq[h][p][c] * sk[h][j][c];
        ss[h][p][j] = s * scale;
    }
    __syncwarp();

    if (lane < S_IN) {
        int p = lane;
        float m = -1e30f;
        #pragma unroll
        for (int j = 0; j < S_IN; j++) m = fmaxf(m, ss[h][p][j]);
        float sum = 0.f;
        #pragma unroll
        for (int j = 0; j < S_IN; j++) { float e = __expf(ss[h][p][j] - m); ss[h][p][j] = e; sum += e; }
        float inv = 1.f / sum;
        #pragma unroll
        for (int j = 0; j < S_IN; j++) ss[h][p][j] *= inv;
    }
    __syncwarp();

    float* op = g_ctx + (size_t)u * CTXI_PER_U + h * (S_IN * DV_I);
    for (int i = lane; i < S_IN * DV_I; i += 32) {
        int p = i / DV_I, c = i % DV_I;
        float s = 0.f;
        #pragma unroll
        for (int j = 0; j < S_IN; j++) s += ss[h][p][j] * sv[h][j][c];
        op[p * DV_I + c] = rnd_tf32(s);      // GEMM A-side input: tf32-rounded
    }
}

// ---------------- weight transpose + tf32 round: W[K][N] -> Wt[N][K] ----------
__global__ void transpose_round(const float* __restrict__ W, float* __restrict__ Wt,
                                int K, int N)
{
    __shared__ float t[32][33];
    int kb = blockIdx.y * 32, nb = blockIdx.x * 32;
    int x = threadIdx.x, y = threadIdx.y;   // 32 x 8
    #pragma unroll
    for (int dy = 0; dy < 32; dy += 8) {
        int k = kb + y + dy, n = nb + x;
        t[y + dy][x] = (k < K && n < N) ? W[(size_t)k * N + n] : 0.f;
    }
    __syncthreads();
    #pragma unroll
    for (int dy = 0; dy < 32; dy += 8) {
        int n = nb + y + dy, k = kb + x;
        if (n < N && k < K) Wt[(size_t)n * K + k] = rnd_tf32(t[x][y + dy]);
    }
}

// ---------------- pack outer qkv weights transposed [768][64] + bias ----------
__global__ void pack_qkv(const float* __restrict__ owq, const float* __restrict__ owk,
                         const float* __restrict__ owv,
                         const float* __restrict__ obq, const float* __restrict__ obk,
                         const float* __restrict__ obv)
{
    int i = blockIdx.x * blockDim.x + threadIdx.x;
    if (i < 768 * 64) {
        int col = i / 64, k = i % 64;
        int sel = col >> 8, hd = col & 255;
        int h = hd >> 6, d = hd & 63;
        const float* w = (sel == 0) ? owq : (sel == 1) ? owk : owv;
        g_wpackT[i] = rnd_tf32(w[(h * 64 + k) * 64 + d]);
    }
    if (i < 768) {
        int sel = i >> 8, hd = i & 255;
        int h = hd >> 6, d = hd & 63;
        const float* b = (sel == 0) ? obq : (sel == 1) ? obk : obv;
        g_bpack[i] = b[h * 64 + d];
    }
}

// ---------------- outer attention: 1 block per (b,h) ----------------
__global__ void outer_attn_kernel()
{
    const int bh = blockIdx.x;         // b*4+h
    const int b  = bh >> 2, h = bh & 3;
    const int tid = threadIdx.x;       // 128

    __shared__ float sq[S_OUT][65], sk[S_OUT][65], sv[S_OUT][65];
    __shared__ float ss[S_OUT][S_OUT];

    for (int i = tid; i < S_OUT * 64; i += blockDim.x) {
        int p = i >> 6, d = i & 63;
        size_t base = (size_t)(b * S_OUT + p) * 768;
        sq[p][d] = g_qkv[base +        h * 64 + d];
        sk[p][d] = g_qkv[base + 256 +  h * 64 + d];
        sv[p][d] = g_qkv[base + 512 +  h * 64 + d];
    }
    __syncthreads();

    for (int i = tid; i < S_OUT * S_OUT; i += blockDim.x) {
        int p = i / S_OUT, j = i % S_OUT;
        float s = 0.f;
        #pragma unroll 16
        for (int c = 0; c < 64; c++) s += sq[p][c] * sk[j][c];
        ss[p][j] = s * 0.125f;
    }
    __syncthreads();

    if (tid < S_OUT) {
        int p = tid;
        float m = -1e30f;
        #pragma unroll
        for (int j = 0; j < S_OUT; j++) m = fmaxf(m, ss[p][j]);
        float sum = 0.f;
        #pragma unroll
        for (int j = 0; j < S_OUT; j++) { float e = __expf(ss[p][j] - m); ss[p][j] = e; sum += e; }
        float inv = 1.f / sum;
        #pragma unroll
        for (int j = 0; j < S_OUT; j++) ss[p][j] *= inv;
    }
    __syncthreads();

    float* op = g_ctxo + (size_t)bh * (S_OUT * 64);
    for (int i = tid; i < S_OUT * 64; i += blockDim.x) {
        int p = i >> 6, c = i & 63;
        float s = 0.f;
        #pragma unroll
        for (int j = 0; j < S_OUT; j++) s += ss[p][j] * sv[j][c];
        op[i] = rnd_tf32(s);
    }
}

// ===== tf32 mma.sync GEMM with float4 fragment loads (k-slot permutation) =====
// C = act(A[M,K] @ Bt[N,K]^T + bias).  128x64 block, BK=16, 256 thr (8 warps
// 4m x 2n, 32x32 warp tile).  cp.async 3-stage ring; smem row-major with chunk
// XOR swizzle c^(row&3) -> LDS.128 conflict-free.  k-slot map per 16-K block:
// group0 {t->4t, t+4->4t+1}, group1 {t->4t+2, t+4->4t+3} (A/B consistent).
// Requires M%128==0, K%4==0, N even.
template<int ACT, int ROUND>
__global__ void __launch_bounds__(256, 2)
gemm_mma(const float* __restrict__ A, const float* __restrict__ Bt,
         const float* __restrict__ bias, float* __restrict__ C,
         int M, int N, int K)
{
    __shared__ float As[3][128][16];
    __shared__ float Bs[3][64][16];

    const int tid  = threadIdx.x;
    const int warp = tid >> 5, lane = tid & 31;
    const int g = lane >> 2, t = lane & 3;
    const int bm = blockIdx.y * 128, bn = blockIdx.x * 64;
    const int wm = (warp >> 1) * 32, wn = (warp & 1) * 32;
    const int niter = (K + 15) / 16;

    const uint32_t sA = smem_u32(&As[0][0][0]);
    const uint32_t sB = smem_u32(&Bs[0][0][0]);

    auto fill = [&](int i) {
        const int s = i % 3, k0 = i * 16;
        #pragma unroll
        for (int c2 = tid; c2 < 512; c2 += 256) {      // A: 128 rows x 4 chunks
            int r = c2 >> 2, c = c2 & 3;
            int koff = k0 + c * 4;
            int ok = koff < K;
            cp16(sA + (((s * 128 + r) * 16 + ((c ^ (r & 3)) << 2)) << 2),
                 A + (size_t)(bm + r) * K + (ok ? koff : 0), ok ? 16 : 0);
        }
        {                                               // B: 64 rows x 4 chunks
            int r = tid >> 2, c = tid & 3;
            int koff = k0 + c * 4;
            int n = bn + r;
            int ok = (n < N) && (koff < K);
            cp16(sB + (((s * 64 + r) * 16 + ((c ^ (r & 3)) << 2)) << 2),
                 Bt + (size_t)(ok ? n : 0) * K + (ok ? koff : 0), ok ? 16 : 0);
        }
        cp_commit();
    };

    float acc[2][4][4] = {};

    fill(0);
    if (niter > 1) fill(1);

    for (int i = 0; i < niter; i++) {
        const int s = i % 3;
        if (i + 1 < niter) cp_wait<1>(); else cp_wait<0>();
        __syncthreads();

        // fragment loads: one LDS.128 per row / per n-tile
        float4 alo[2], ahi[2], bf[4];
        #pragma unroll
        for (int mt = 0; mt < 2; mt++) {
            int r0 = wm + mt * 16 + g, r1 = r0 + 8;
            alo[mt] = *reinterpret_cast<const float4*>(&As[s][r0][(t ^ (r0 & 3)) << 2]);
            ahi[mt] = *reinterpret_cast<const float4*>(&As[s][r1][(t ^ (r1 & 3)) << 2]);
        }
        #pragma unroll
        for (int nt = 0; nt < 4; nt++) {
            int n = wn + nt * 8 + g;
            bf[nt] = *reinterpret_cast<const float4*>(&Bs[s][n][(t ^ (n & 3)) << 2]);
        }
        #pragma unroll
        for (int mt = 0; mt < 2; mt++)
            #pragma unroll
            for (int nt = 0; nt < 4; nt++) {
                mma_tf32(acc[mt][nt],
                         __float_as_uint(alo[mt].x), __float_as_uint(ahi[mt].x),
                         __float_as_uint(alo[mt].y), __float_as_uint(ahi[mt].y),
                         __float_as_uint(bf[nt].x),  __float_as_uint(bf[nt].y));
                mma_tf32(acc[mt][nt],
                         __float_as_uint(alo[mt].z), __float_as_uint(ahi[mt].z),
                         __float_as_uint(alo[mt].w), __float_as_uint(ahi[mt].w),
                         __float_as_uint(bf[nt].z),  __float_as_uint(bf[nt].w));
            }

        __syncthreads();
        if (i + 2 < niter) fill(i + 2);
    }

    // epilogue: acc[mt][nt] -> rows (g, g+8), cols (2t, 2t+1)
    #pragma unroll
    for (int mt = 0; mt < 2; mt++) {
        #pragma unroll
        for (int nt = 0; nt < 4; nt++) {
            int row0 = bm + wm + mt * 16 + g;
            int col  = bn + wn + nt * 8 + 2 * t;
            if (col >= N) continue;
            float b0 = bias[col], b1 = bias[col + 1];
            #pragma unroll
            for (int half = 0; half < 2; half++) {
                int r = row0 + half * 8;
                float2 v;
                v.x = acc[mt][nt][half * 2 + 0] + b0;
                v.y = acc[mt][nt][half * 2 + 1] + b1;
                if (ACT)   { v.x = tanh_fast(v.x); v.y = tanh_fast(v.y); }
                if (ROUND) { v.x = rnd_tf32(v.x);  v.y = rnd_tf32(v.y); }
                *reinterpret_cast<float2*>(C + (size_t)r * N + col) = v;
            }
        }
    }
}

static inline int cdiv(int a, int b) { return (a + b - 1) / b; }

extern "C" void kernel_launch(void* const* d_in, const int* in_sizes, int n_in,
                              void* d_out, int out_size)
{
    (void)in_sizes; (void)n_in; (void)out_size;
    const float* x   = (const float*)d_in[0];
    const float* iwq = (const float*)d_in[1];
    const float* ibq = (const float*)d_in[2];
    const float* iwk = (const float*)d_in[3];
    const float* ibk = (const float*)d_in[4];
    const float* iwv = (const float*)d_in[5];
    const float* ibv = (const float*)d_in[6];
    const float* iw1 = (const float*)d_in[7];
    const float* ib1 = (const float*)d_in[8];
    const float* iw2 = (const float*)d_in[9];
    const float* ib2 = (const float*)d_in[10];
    const float* owq = (const float*)d_in[11];
    const float* obq = (const float*)d_in[12];
    const float* owk = (const float*)d_in[13];
    const float* obk = (const float*)d_in[14];
    const float* owv = (const float*)d_in[15];
    const float* obv = (const float*)d_in[16];
    const float* ow1 = (const float*)d_in[17];
    const float* ob1 = (const float*)d_in[18];
    const float* ow2 = (const float*)d_in[19];
    const float* ob2 = (const float*)d_in[20];
    float* out = (float*)d_out;

    float *p_ctx, *p_h1, *p_seq, *p_wpT, *p_bp, *p_qkv, *p_ctxo, *p_h2;
    float *p_w1t, *p_w2t, *p_w3t, *p_w4t;
    cudaGetSymbolAddress((void**)&p_ctx,  g_ctx);
    cudaGetSymbolAddress((void**)&p_h1,   g_h1);
    cudaGetSymbolAddress((void**)&p_seq,  g_seq);
    cudaGetSymbolAddress((void**)&p_wpT,  g_wpackT);
    cudaGetSymbolAddress((void**)&p_bp,   g_bpack);
    cudaGetSymbolAddress((void**)&p_qkv,  g_qkv);
    cudaGetSymbolAddress((void**)&p_ctxo, g_ctxo);
    cudaGetSymbolAddress((void**)&p_h2,   g_h2);
    cudaGetSymbolAddress((void**)&p_w1t,  g_w1t);
    cudaGetSymbolAddress((void**)&p_w2t,  g_w2t);
    cudaGetSymbolAddress((void**)&p_w3t,  g_w3t);
    cudaGetSymbolAddress((void**)&p_w4t,  g_w4t);

    // 0) inner attention -> g_ctx [122880][136] (tf32-rounded)
    inner_attn_kernel<<<NU, 128>>>(x, iwq, ibq, iwk, ibk, iwv, ibv);

    // 1,2) transposes needed for inner GEMMs
    transpose_round<<<dim3(cdiv(256, 32),  cdiv(136, 32)),  dim3(32, 8)>>>(iw1, p_w1t, 136, 256);
    transpose_round<<<dim3(cdiv(64, 32),   cdiv(1024, 32)), dim3(32, 8)>>>(iw2, p_w2t, 1024, 64);

    // 3) fc1_i: [122880,136] @ w1t[256,136]^T + tanh -> g_h1   (ncu capture slot)
    gemm_mma<1, 1><<<dim3(4, FC1I_M / 128), 256>>>(p_ctx, p_w1t, ib1, p_h1, FC1I_M, 256, 136);

    // 4) fc2_i: [30720,1024] @ w2t[64,1024]^T -> g_seq
    gemm_mma<0, 1><<<dim3(1, NU / 128), 256>>>(p_h1, p_w2t, ib2, p_seq, NU, 64, 1024);

    // 5) pack outer qkv (transposed, rounded)
    pack_qkv<<<cdiv(768 * 64, 256), 256>>>(owq, owk, owv, obq, obk, obv);

    // 6) outer qkv: [30720,64] @ wpackT[768,64]^T -> g_qkv
    gemm_mma<0, 0><<<dim3(12, NU / 128), 256>>>(p_seq, p_wpT, p_bp, p_qkv, NU, 768, 64);

    // 7) outer attention -> g_ctxo [4096][1920] (rounded)
    outer_attn_kernel<<<BB * HH, 128>>>();

    // 8,9) transposes for outer GEMMs
    transpose_round<<<dim3(cdiv(1024, 32), cdiv(1920, 32)), dim3(32, 8)>>>(ow1, p_w3t, 1920, 1024);
    transpose_round<<<dim3(cdiv(1080, 32), cdiv(4096, 32)), dim3(32, 8)>>>(ow2, p_w4t, 4096, 1080);

    // 10) fc1_o: [4096,1920] @ w3t[1024,1920]^T + tanh -> g_h2
    gemm_mma<1, 1><<<dim3(16, (BB * HH) / 128), 256>>>(p_ctxo, p_w3t, ob1, p_h2, BB * HH, 1024, 1920);

    // 11) fc2_o: [1024,4096] @ w4t[1080,4096]^T -> out
    gemm_mma<0, 0><<<dim3(cdiv(OUT_O, 64), BB / 128), 256>>>(p_h2, p_w4t, ob2, out, BB, OUT_O, HH * HID_O);
}

// round 6
// speedup vs baseline: 2.5418x; 1.0358x over previous
#include <cuda_runtime.h>
#include <cuda_bf16.h>
#include <cstdint>

// ---------------- problem constants ----------------
#define BB      1024
#define S_OUT   30
#define S_IN    17
#define D_INN   3
#define HH      4
#define DKQ_I   6
#define DV_I    8
#define HID_I   256
#define OUT_I   64
#define HID_O   1024
#define OUT_O   1080

#define NU      (BB * S_OUT)          // 30720 inner units
#define CTXI_PER_U (HH * S_IN * DV_I) // 544
#define FC1I_M  (NU * HH)             // 122880
#define FC1I_K  (S_IN * DV_I)         // 136

// ---------------- scratch (device globals; no runtime allocation) -------------
__device__ float g_ctx  [(size_t)NU * CTXI_PER_U + 64];   // [122880][136]
__device__ float g_h1   [(size_t)FC1I_M * HID_I];         // [30720][1024]
__device__ float g_seq  [(size_t)NU * 64];                // [30720][64]
__device__ float g_wpackT[768 * 64];                      // [n=768][k=64] rounded
__device__ float g_bpack[768];
__device__ float g_qkv  [(size_t)NU * 768];               // [30720][768]
__device__ float g_ctxo [(size_t)BB * HH * S_OUT * 64];   // [4096][1920]
__device__ float g_h2   [(size_t)BB * HH * HID_O];        // [1024][4096]
// transposed + tf32-rounded weights ([N][K])
__device__ float g_w1t[256 * 136];
__device__ float g_w2t[64 * 1024];
__device__ float g_w3t[1024 * 1920];
__device__ float g_w4t[1080 * 4096];

// ---------------- helpers ----------------
__device__ __forceinline__ float tanh_fast(float x) {
    float y; asm("tanh.approx.f32 %0, %1;" : "=f"(y) : "f"(x)); return y;
}
// round fp32 -> tf32 precision (RNA when followed by HW truncation of low 13 bits)
__device__ __forceinline__ float rnd_tf32(float f) {
    return __uint_as_float(__float_as_uint(f) + 0x1000u);
}
__device__ __forceinline__ uint32_t smem_u32(const void* p) {
    uint32_t a;
    asm("{ .reg .u64 t; cvta.to.shared.u64 t, %1; cvt.u32.u64 %0, t; }" : "=r"(a) : "l"(p));
    return a;
}
__device__ __forceinline__ void cp16(uint32_t dst, const void* src, int sz) {
    asm volatile("cp.async.cg.shared.global [%0], [%1], 16, %2;"
                 :: "r"(dst), "l"(src), "r"(sz) : "memory");
}
__device__ __forceinline__ void cp_commit() {
    asm volatile("cp.async.commit_group;" ::: "memory");
}
template<int N> __device__ __forceinline__ void cp_wait() {
    asm volatile("cp.async.wait_group %0;" :: "n"(N) : "memory");
}
__device__ __forceinline__ void mma_tf32(float c[4], uint32_t a0, uint32_t a1,
                                         uint32_t a2, uint32_t a3,
                                         uint32_t b0, uint32_t b1) {
    asm volatile(
        "mma.sync.aligned.m16n8k8.row.col.f32.tf32.tf32.f32 "
        "{%0,%1,%2,%3}, {%4,%5,%6,%7}, {%8,%9}, {%0,%1,%2,%3};"
        : "+f"(c[0]), "+f"(c[1]), "+f"(c[2]), "+f"(c[3])
        : "r"(a0), "r"(a1), "r"(a2), "r"(a3), "r"(b0), "r"(b1));
}

// ---------------- inner attention: 1 block per (b,s_out), 1 warp per head -----
__global__ void inner_attn_kernel(const float* __restrict__ x,
                                  const float* __restrict__ iwq, const float* __restrict__ ibq,
                                  const float* __restrict__ iwk, const float* __restrict__ ibk,
                                  const float* __restrict__ iwv, const float* __restrict__ ibv)
{
    const int u    = blockIdx.x;
    const int tid  = threadIdx.x;
    const int h    = tid >> 5;
    const int lane = tid & 31;

    __shared__ float sx[S_IN * D_INN];
    __shared__ float sq[HH][S_IN][DKQ_I];
    __shared__ float sk[HH][S_IN][DKQ_I];
    __shared__ float sv[HH][S_IN][DV_I];
    __shared__ float ss[HH][S_IN][S_IN];

    const float* xp = x + (size_t)u * (S_IN * D_INN);
    if (tid < S_IN * D_INN) sx[tid] = xp[tid];
    __syncthreads();

    for (int i = lane; i < S_IN * (2 * DKQ_I + DV_I); i += 32) {
        if (i < S_IN * DKQ_I) {
            int p = i / DKQ_I, c = i % DKQ_I;
            float s = ibq[h * DKQ_I + c];
            #pragma unroll
            for (int d = 0; d < D_INN; d++)
                s += sx[p * D_INN + d] * iwq[(h * D_INN + d) * DKQ_I + c];
            sq[h][p][c] = s;
        } else if (i < 2 * S_IN * DKQ_I) {
            int j = i - S_IN * DKQ_I;
            int p = j / DKQ_I, c = j % DKQ_I;
            float s = ibk[h * DKQ_I + c];
            #pragma unroll
            for (int d = 0; d < D_INN; d++)
                s += sx[p * D_INN + d] * iwk[(h * D_INN + d) * DKQ_I + c];
            sk[h][p][c] = s;
        } else {
            int j = i - 2 * S_IN * DKQ_I;
            int p = j / DV_I, c = j % DV_I;
            float s = ibv[h * DV_I + c];
            #pragma unroll
            for (int d = 0; d < D_INN; d++)
                s += sx[p * D_INN + d] * iwv[(h * D_INN + d) * DV_I + c];
            sv[h][p][c] = s;
        }
    }
    __syncwarp();

    const float scale = 0.40824829046386302f;   // 1/sqrt(6)
    for (int i = lane; i < S_IN * S_IN; i += 32) {
        int p = i / S_IN, j = i % S_IN;
        float s = 0.f;
        #pragma unroll
        for (int c = 0; c < DKQ_I; c++) s += sq[h][p][c] * sk[h][j][c];
        ss[h][p][j] = s * scale;
    }
    __syncwarp();

    if (lane < S_IN) {
        int p = lane;
        float m = -1e30f;
        #pragma unroll
        for (int j = 0; j < S_IN; j++) m = fmaxf(m, ss[h][p][j]);
        float sum = 0.f;
        #pragma unroll
        for (int j = 0; j < S_IN; j++) { float e = __expf(ss[h][p][j] - m); ss[h][p][j] = e; sum += e; }
        float inv = 1.f / sum;
        #pragma unroll
        for (int j = 0; j < S_IN; j++) ss[h][p][j] *= inv;
    }
    __syncwarp();

    float* op = g_ctx + (size_t)u * CTXI_PER_U + h * (S_IN * DV_I);
    for (int i = lane; i < S_IN * DV_I; i += 32) {
        int p = i / DV_I, c = i % DV_I;
        float s = 0.f;
        #pragma unroll
        for (int j = 0; j < S_IN; j++) s += ss[h][p][j] * sv[h][j][c];
        op[p * DV_I + c] = rnd_tf32(s);      // GEMM A-side input: tf32-rounded
    }
}

// ---------------- weight transpose + tf32 round: W[K][N] -> Wt[N][K] ----------
__global__ void transpose_round(const float* __restrict__ W, float* __restrict__ Wt,
                                int K, int N)
{
    __shared__ float t[32][33];
    int kb = blockIdx.y * 32, nb = blockIdx.x * 32;
    int x = threadIdx.x, y = threadIdx.y;   // 32 x 8
    #pragma unroll
    for (int dy = 0; dy < 32; dy += 8) {
        int k = kb + y + dy, n = nb + x;
        t[y + dy][x] = (k < K && n < N) ? W[(size_t)k * N + n] : 0.f;
    }
    __syncthreads();
    #pragma unroll
    for (int dy = 0; dy < 32; dy += 8) {
        int n = nb + y + dy, k = kb + x;
        if (n < N && k < K) Wt[(size_t)n * K + k] = rnd_tf32(t[x][y + dy]);
    }
}

// ---------------- pack outer qkv weights transposed [768][64] + bias ----------
__global__ void pack_qkv(const float* __restrict__ owq, const float* __restrict__ owk,
                         const float* __restrict__ owv,
                         const float* __restrict__ obq, const float* __restrict__ obk,
                         const float* __restrict__ obv)
{
    int i = blockIdx.x * blockDim.x + threadIdx.x;
    if (i < 768 * 64) {
        int col = i / 64, k = i % 64;
        int sel = col >> 8, hd = col & 255;
        int h = hd >> 6, d = hd & 63;
        const float* w = (sel == 0) ? owq : (sel == 1) ? owk : owv;
        g_wpackT[i] = rnd_tf32(w[(h * 64 + k) * 64 + d]);
    }
    if (i < 768) {
        int sel = i >> 8, hd = i & 255;
        int h = hd >> 6, d = hd & 63;
        const float* b = (sel == 0) ? obq : (sel == 1) ? obk : obv;
        g_bpack[i] = b[h * 64 + d];
    }
}

// ---------------- outer attention: 1 block per (b,h) ----------------
__global__ void outer_attn_kernel()
{
    const int bh = blockIdx.x;         // b*4+h
    const int b  = bh >> 2, h = bh & 3;
    const int tid = threadIdx.x;       // 128

    __shared__ float sq[S_OUT][65], sk[S_OUT][65], sv[S_OUT][65];
    __shared__ float ss[S_OUT][S_OUT];

    for (int i = tid; i < S_OUT * 64; i += blockDim.x) {
        int p = i >> 6, d = i & 63;
        size_t base = (size_t)(b * S_OUT + p) * 768;
        sq[p][d] = g_qkv[base +        h * 64 + d];
        sk[p][d] = g_qkv[base + 256 +  h * 64 + d];
        sv[p][d] = g_qkv[base + 512 +  h * 64 + d];
    }
    __syncthreads();

    for (int i = tid; i < S_OUT * S_OUT; i += blockDim.x) {
        int p = i / S_OUT, j = i % S_OUT;
        float s = 0.f;
        #pragma unroll 16
        for (int c = 0; c < 64; c++) s += sq[p][c] * sk[j][c];
        ss[p][j] = s * 0.125f;
    }
    __syncthreads();

    if (tid < S_OUT) {
        int p = tid;
        float m = -1e30f;
        #pragma unroll
        for (int j = 0; j < S_OUT; j++) m = fmaxf(m, ss[p][j]);
        float sum = 0.f;
        #pragma unroll
        for (int j = 0; j < S_OUT; j++) { float e = __expf(ss[p][j] - m); ss[p][j] = e; sum += e; }
        float inv = 1.f / sum;
        #pragma unroll
        for (int j = 0; j < S_OUT; j++) ss[p][j] *= inv;
    }
    __syncthreads();

    float* op = g_ctxo + (size_t)bh * (S_OUT * 64);
    for (int i = tid; i < S_OUT * 64; i += blockDim.x) {
        int p = i >> 6, c = i & 63;
        float s = 0.f;
        #pragma unroll
        for (int j = 0; j < S_OUT; j++) s += ss[p][j] * sv[j][c];
        op[i] = rnd_tf32(s);
    }
}

// ===== tf32 mma.sync GEMM, 128 x NT block, 8 warps as 2m x 4n (64 x NT/4) =====
// C = act(A[M,K] @ Bt[N,K]^T + bias).  BK=16, 3-stage cp.async ring.
// k-slot permutation (A/B consistent) -> all fragment loads are LDS.128,
// chunk XOR swizzle c^(row&3) keeps them conflict-free.
// Requires M%128==0, K%4==0, N even.
template<int NT, int ACT, int ROUND, int MAXB>
__global__ void __launch_bounds__(256, MAXB)
gemm_mma(const float* __restrict__ A, const float* __restrict__ Bt,
         const float* __restrict__ bias, float* __restrict__ C,
         int M, int N, int K)
{
    constexpr int NSUB = NT / 32;          // B n-subtiles per warp (4 or 2)
    __shared__ float As[3][128][16];
    __shared__ float Bs[3][NT][16];

    const int tid  = threadIdx.x;
    const int warp = tid >> 5, lane = tid & 31;
    const int g = lane >> 2, t = lane & 3;
    const int bm = blockIdx.y * 128, bn = blockIdx.x * NT;
    const int wm = (warp & 1) * 64;                 // warp m offset (64 rows)
    const int wn = (warp >> 1) * (NT / 4);          // warp n offset
    const int niter = (K + 15) / 16;

    const uint32_t sA = smem_u32(&As[0][0][0]);
    const uint32_t sB = smem_u32(&Bs[0][0][0]);

    auto fill = [&](int i) {
        const int s = i % 3, k0 = i * 16;
        #pragma unroll
        for (int c2 = tid; c2 < 512; c2 += 256) {      // A: 128 rows x 4 chunks
            int r = c2 >> 2, c = c2 & 3;
            int koff = k0 + c * 4;
            int ok = koff < K;
            cp16(sA + (((s * 128 + r) * 16 + ((c ^ (r & 3)) << 2)) << 2),
                 A + (size_t)(bm + r) * K + (ok ? koff : 0), ok ? 16 : 0);
        }
        #pragma unroll
        for (int c2 = tid; c2 < NT * 4; c2 += 256) {   // B: NT rows x 4 chunks
            int r = c2 >> 2, c = c2 & 3;
            int koff = k0 + c * 4;
            int n = bn + r;
            int ok = (n < N) && (koff < K);
            cp16(sB + (((s * NT + r) * 16 + ((c ^ (r & 3)) << 2)) << 2),
                 Bt + (size_t)(ok ? n : 0) * K + (ok ? koff : 0), ok ? 16 : 0);
        }
        cp_commit();
    };

    float acc[4][NSUB][4] = {};

    fill(0);
    if (niter > 1) fill(1);

    for (int i = 0; i < niter; i++) {
        const int s = i % 3;
        if (i + 1 < niter) cp_wait<1>(); else cp_wait<0>();
        __syncthreads();

        float4 alo[4], ahi[4], bf[NSUB];
        #pragma unroll
        for (int mt = 0; mt < 4; mt++) {
            int r0 = wm + mt * 16 + g, r1 = r0 + 8;
            alo[mt] = *reinterpret_cast<const float4*>(&As[s][r0][(t ^ (r0 & 3)) << 2]);
            ahi[mt] = *reinterpret_cast<const float4*>(&As[s][r1][(t ^ (r1 & 3)) << 2]);
        }
        #pragma unroll
        for (int nt = 0; nt < NSUB; nt++) {
            int n = wn + nt * 8 + g;
            bf[nt] = *reinterpret_cast<const float4*>(&Bs[s][n][(t ^ (n & 3)) << 2]);
        }
        #pragma unroll
        for (int mt = 0; mt < 4; mt++)
            #pragma unroll
            for (int nt = 0; nt < NSUB; nt++) {
                mma_tf32(acc[mt][nt],
                         __float_as_uint(alo[mt].x), __float_as_uint(ahi[mt].x),
                         __float_as_uint(alo[mt].y), __float_as_uint(ahi[mt].y),
                         __float_as_uint(bf[nt].x),  __float_as_uint(bf[nt].y));
                mma_tf32(acc[mt][nt],
                         __float_as_uint(alo[mt].z), __float_as_uint(ahi[mt].z),
                         __float_as_uint(alo[mt].w), __float_as_uint(ahi[mt].w),
                         __float_as_uint(bf[nt].z),  __float_as_uint(bf[nt].w));
            }

        __syncthreads();
        if (i + 2 < niter) fill(i + 2);
    }

    // epilogue: acc[mt][nt] -> rows (g, g+8), cols (2t, 2t+1)
    #pragma unroll
    for (int mt = 0; mt < 4; mt++) {
        #pragma unroll
        for (int nt = 0; nt < NSUB; nt++) {
            int row0 = bm + wm + mt * 16 + g;
            int col  = bn + wn + nt * 8 + 2 * t;
            if (col >= N) continue;
            float b0 = bias[col], b1 = bias[col + 1];
            #pragma unroll
            for (int half = 0; half < 2; half++) {
                int r = row0 + half * 8;
                float2 v;
                v.x = acc[mt][nt][half * 2 + 0] + b0;
                v.y = acc[mt][nt][half * 2 + 1] + b1;
                if (ACT)   { v.x = tanh_fast(v.x); v.y = tanh_fast(v.y); }
                if (ROUND) { v.x = rnd_tf32(v.x);  v.y = rnd_tf32(v.y); }
                *reinterpret_cast<float2*>(C + (size_t)r * N + col) = v;
            }
        }
    }
}

static inline int cdiv(int a, int b) { return (a + b - 1) / b; }

extern "C" void kernel_launch(void* const* d_in, const int* in_sizes, int n_in,
                              void* d_out, int out_size)
{
    (void)in_sizes; (void)n_in; (void)out_size;
    const float* x   = (const float*)d_in[0];
    const float* iwq = (const float*)d_in[1];
    const float* ibq = (const float*)d_in[2];
    const float* iwk = (const float*)d_in[3];
    const float* ibk = (const float*)d_in[4];
    const float* iwv = (const float*)d_in[5];
    const float* ibv = (const float*)d_in[6];
    const float* iw1 = (const float*)d_in[7];
    const float* ib1 = (const float*)d_in[8];
    const float* iw2 = (const float*)d_in[9];
    const float* ib2 = (const float*)d_in[10];
    const float* owq = (const float*)d_in[11];
    const float* obq = (const float*)d_in[12];
    const float* owk = (const float*)d_in[13];
    const float* obk = (const float*)d_in[14];
    const float* owv = (const float*)d_in[15];
    const float* obv = (const float*)d_in[16];
    const float* ow1 = (const float*)d_in[17];
    const float* ob1 = (const float*)d_in[18];
    const float* ow2 = (const float*)d_in[19];
    const float* ob2 = (const float*)d_in[20];
    float* out = (float*)d_out;

    float *p_ctx, *p_h1, *p_seq, *p_wpT, *p_bp, *p_qkv, *p_ctxo, *p_h2;
    float *p_w1t, *p_w2t, *p_w3t, *p_w4t;
    cudaGetSymbolAddress((void**)&p_ctx,  g_ctx);
    cudaGetSymbolAddress((void**)&p_h1,   g_h1);
    cudaGetSymbolAddress((void**)&p_seq,  g_seq);
    cudaGetSymbolAddress((void**)&p_wpT,  g_wpackT);
    cudaGetSymbolAddress((void**)&p_bp,   g_bpack);
    cudaGetSymbolAddress((void**)&p_qkv,  g_qkv);
    cudaGetSymbolAddress((void**)&p_ctxo, g_ctxo);
    cudaGetSymbolAddress((void**)&p_h2,   g_h2);
    cudaGetSymbolAddress((void**)&p_w1t,  g_w1t);
    cudaGetSymbolAddress((void**)&p_w2t,  g_w2t);
    cudaGetSymbolAddress((void**)&p_w3t,  g_w3t);
    cudaGetSymbolAddress((void**)&p_w4t,  g_w4t);

    // 0) inner attention -> g_ctx [122880][136] (tf32-rounded)
    inner_attn_kernel<<<NU, 128>>>(x, iwq, ibq, iwk, ibk, iwv, ibv);

    // 1,2) transposes needed for inner GEMMs
    transpose_round<<<dim3(cdiv(256, 32),  cdiv(136, 32)),  dim3(32, 8)>>>(iw1, p_w1t, 136, 256);
    transpose_round<<<dim3(cdiv(64, 32),   cdiv(1024, 32)), dim3(32, 8)>>>(iw2, p_w2t, 1024, 64);

    // 3) fc1_i: [122880,136] @ w1t[256,136]^T + tanh -> g_h1   (ncu capture slot)
    gemm_mma<128, 1, 1, 1><<<dim3(2, FC1I_M / 128), 256>>>(p_ctx, p_w1t, ib1, p_h1, FC1I_M, 256, 136);

    // 4) fc2_i: [30720,1024] @ w2t[64,1024]^T -> g_seq
    gemm_mma<64, 0, 1, 2><<<dim3(1, NU / 128), 256>>>(p_h1, p_w2t, ib2, p_seq, NU, 64, 1024);

    // 5) pack outer qkv (transposed, rounded)
    pack_qkv<<<cdiv(768 * 64, 256), 256>>>(owq, owk, owv, obq, obk, obv);

    // 6) outer qkv: [30720,64] @ wpackT[768,64]^T -> g_qkv
    gemm_mma<128, 0, 0, 1><<<dim3(6, NU / 128), 256>>>(p_seq, p_wpT, p_bp, p_qkv, NU, 768, 64);

    // 7) outer attention -> g_ctxo [4096][1920] (rounded)
    outer_attn_kernel<<<BB * HH, 128>>>();

    // 8,9) transposes for outer GEMMs
    transpose_round<<<dim3(cdiv(1024, 32), cdiv(1920, 32)), dim3(32, 8)>>>(ow1, p_w3t, 1920, 1024);
    transpose_round<<<dim3(cdiv(1080, 32), cdiv(4096, 32)), dim3(32, 8)>>>(ow2, p_w4t, 4096, 1080);

    // 10) fc1_o: [4096,1920] @ w3t[1024,1920]^T + tanh -> g_h2
    gemm_mma<128, 1, 1, 1><<<dim3(8, (BB * HH) / 128), 256>>>(p_ctxo, p_w3t, ob1, p_h2, BB * HH, 1024, 1920);

    // 11) fc2_o: [1024,4096] @ w4t[1080,4096]^T -> out
    gemm_mma<128, 0, 0, 1><<<dim3(cdiv(OUT_O, 128), BB / 128), 256>>>(p_h2, p_w4t, ob2, out, BB, OUT_O, HH * HID_O);
}

// round 7
// speedup vs baseline: 2.5939x; 1.0205x over previous
#include <cuda_runtime.h>
#include <cuda_bf16.h>
#include <cstdint>

// ---------------- problem constants ----------------
#define BB      1024
#define S_OUT   30
#define S_IN    17
#define D_INN   3
#define HH      4
#define DKQ_I   6
#define DV_I    8
#define HID_I   256
#define OUT_I   64
#define HID_O   1024
#define OUT_O   1080

#define NU      (BB * S_OUT)          // 30720 inner units
#define CTXI_PER_U (HH * S_IN * DV_I) // 544
#define FC1I_M  (NU * HH)             // 122880
#define FC1I_K  (S_IN * DV_I)         // 136

// ---------------- scratch (device globals; no runtime allocation) -------------
__device__ float g_ctx  [(size_t)NU * CTXI_PER_U + 64];   // [122880][136]
__device__ float g_h1   [(size_t)FC1I_M * HID_I];         // [30720][1024]
__device__ float g_seq  [(size_t)NU * 64];                // [30720][64]
__device__ float g_wpackT[768 * 64];                      // [n=768][k=64] rounded
__device__ float g_bpack[768];
__device__ float g_qkv  [(size_t)NU * 768];               // [30720][768]
__device__ float g_ctxo [(size_t)BB * HH * S_OUT * 64];   // [4096][1920]
__device__ float g_h2   [(size_t)BB * HH * HID_O];        // [1024][4096]
// transposed + tf32-rounded weights ([N][K])
__device__ float g_w1t[256 * 136];
__device__ float g_w2t[64 * 1024];
__device__ float g_w3t[1024 * 1920];
__device__ float g_w4t[1080 * 4096];

// ---------------- helpers ----------------
__device__ __forceinline__ float tanh_fast(float x) {
    float y; asm("tanh.approx.f32 %0, %1;" : "=f"(y) : "f"(x)); return y;
}
// round fp32 -> tf32 precision (RNA when followed by HW truncation of low 13 bits)
__device__ __forceinline__ float rnd_tf32(float f) {
    return __uint_as_float(__float_as_uint(f) + 0x1000u);
}
__device__ __forceinline__ uint32_t smem_u32(const void* p) {
    uint32_t a;
    asm("{ .reg .u64 t; cvta.to.shared.u64 t, %1; cvt.u32.u64 %0, t; }" : "=r"(a) : "l"(p));
    return a;
}
__device__ __forceinline__ void cp16(uint32_t dst, const void* src, int sz) {
    asm volatile("cp.async.cg.shared.global [%0], [%1], 16, %2;"
                 :: "r"(dst), "l"(src), "r"(sz) : "memory");
}
__device__ __forceinline__ void cp_commit() {
    asm volatile("cp.async.commit_group;" ::: "memory");
}
template<int N> __device__ __forceinline__ void cp_wait() {
    asm volatile("cp.async.wait_group %0;" :: "n"(N) : "memory");
}
__device__ __forceinline__ void mma_tf32(float c[4], uint32_t a0, uint32_t a1,
                                         uint32_t a2, uint32_t a3,
                                         uint32_t b0, uint32_t b1) {
    asm volatile(
        "mma.sync.aligned.m16n8k8.row.col.f32.tf32.tf32.f32 "
        "{%0,%1,%2,%3}, {%4,%5,%6,%7}, {%8,%9}, {%0,%1,%2,%3};"
        : "+f"(c[0]), "+f"(c[1]), "+f"(c[2]), "+f"(c[3])
        : "r"(a0), "r"(a1), "r"(a2), "r"(a3), "r"(b0), "r"(b1));
}

// ---------------- inner attention: 1 block per (b,s_out), 1 warp per head -----
__global__ void inner_attn_kernel(const float* __restrict__ x,
                                  const float* __restrict__ iwq, const float* __restrict__ ibq,
                                  const float* __restrict__ iwk, const float* __restrict__ ibk,
                                  const float* __restrict__ iwv, const float* __restrict__ ibv)
{
    const int u    = blockIdx.x;
    const int tid  = threadIdx.x;
    const int h    = tid >> 5;
    const int lane = tid & 31;

    __shared__ float sx[S_IN * D_INN];
    __shared__ float sq[HH][S_IN][DKQ_I];
    __shared__ float sk[HH][S_IN][DKQ_I];
    __shared__ float sv[HH][S_IN][DV_I];
    __shared__ float ss[HH][S_IN][S_IN];

    const float* xp = x + (size_t)u * (S_IN * D_INN);
    if (tid < S_IN * D_INN) sx[tid] = xp[tid];
    __syncthreads();

    for (int i = lane; i < S_IN * (2 * DKQ_I + DV_I); i += 32) {
        if (i < S_IN * DKQ_I) {
            int p = i / DKQ_I, c = i % DKQ_I;
            float s = ibq[h * DKQ_I + c];
            #pragma unroll
            for (int d = 0; d < D_INN; d++)
                s += sx[p * D_INN + d] * iwq[(h * D_INN + d) * DKQ_I + c];
            sq[h][p][c] = s;
        } else if (i < 2 * S_IN * DKQ_I) {
            int j = i - S_IN * DKQ_I;
            int p = j / DKQ_I, c = j % DKQ_I;
            float s = ibk[h * DKQ_I + c];
            #pragma unroll
            for (int d = 0; d < D_INN; d++)
                s += sx[p * D_INN + d] * iwk[(h * D_INN + d) * DKQ_I + c];
            sk[h][p][c] = s;
        } else {
            int j = i - 2 * S_IN * DKQ_I;
            int p = j / DV_I, c = j % DV_I;
            float s = ibv[h * DV_I + c];
            #pragma unroll
            for (int d = 0; d < D_INN; d++)
                s += sx[p * D_INN + d] * iwv[(h * D_INN + d) * DV_I + c];
            sv[h][p][c] = s;
        }
    }
    __syncwarp();

    const float scale = 0.40824829046386302f;   // 1/sqrt(6)
    for (int i = lane; i < S_IN * S_IN; i += 32) {
        int p = i / S_IN, j = i % S_IN;
        float s = 0.f;
        #pragma unroll
        for (int c = 0; c < DKQ_I; c++) s += sq[h][p][c] * sk[h][j][c];
        ss[h][p][j] = s * scale;
    }
    __syncwarp();

    if (lane < S_IN) {
        int p = lane;
        float m = -1e30f;
        #pragma unroll
        for (int j = 0; j < S_IN; j++) m = fmaxf(m, ss[h][p][j]);
        float sum = 0.f;
        #pragma unroll
        for (int j = 0; j < S_IN; j++) { float e = __expf(ss[h][p][j] - m); ss[h][p][j] = e; sum += e; }
        float inv = 1.f / sum;
        #pragma unroll
        for (int j = 0; j < S_IN; j++) ss[h][p][j] *= inv;
    }
    __syncwarp();

    float* op = g_ctx + (size_t)u * CTXI_PER_U + h * (S_IN * DV_I);
    for (int i = lane; i < S_IN * DV_I; i += 32) {
        int p = i / DV_I, c = i % DV_I;
        float s = 0.f;
        #pragma unroll
        for (int j = 0; j < S_IN; j++) s += ss[h][p][j] * sv[h][j][c];
        op[p * DV_I + c] = rnd_tf32(s);      // GEMM A-side input: tf32-rounded
    }
}

// ---------------- weight transpose + tf32 round: W[K][N] -> Wt[N][K] ----------
__global__ void transpose_round(const float* __restrict__ W, float* __restrict__ Wt,
                                int K, int N)
{
    __shared__ float t[32][33];
    int kb = blockIdx.y * 32, nb = blockIdx.x * 32;
    int x = threadIdx.x, y = threadIdx.y;   // 32 x 8
    #pragma unroll
    for (int dy = 0; dy < 32; dy += 8) {
        int k = kb + y + dy, n = nb + x;
        t[y + dy][x] = (k < K && n < N) ? W[(size_t)k * N + n] : 0.f;
    }
    __syncthreads();
    #pragma unroll
    for (int dy = 0; dy < 32; dy += 8) {
        int n = nb + y + dy, k = kb + x;
        if (n < N && k < K) Wt[(size_t)n * K + k] = rnd_tf32(t[x][y + dy]);
    }
}

// ---------------- pack outer qkv weights transposed [768][64] + bias ----------
__global__ void pack_qkv(const float* __restrict__ owq, const float* __restrict__ owk,
                         const float* __restrict__ owv,
                         const float* __restrict__ obq, const float* __restrict__ obk,
                         const float* __restrict__ obv)
{
    int i = blockIdx.x * blockDim.x + threadIdx.x;
    if (i < 768 * 64) {
        int col = i / 64, k = i % 64;
        int sel = col >> 8, hd = col & 255;
        int h = hd >> 6, d = hd & 63;
        const float* w = (sel == 0) ? owq : (sel == 1) ? owk : owv;
        g_wpackT[i] = rnd_tf32(w[(h * 64 + k) * 64 + d]);
    }
    if (i < 768) {
        int sel = i >> 8, hd = i & 255;
        int h = hd >> 6, d = hd & 63;
        const float* b = (sel == 0) ? obq : (sel == 1) ? obk : obv;
        g_bpack[i] = b[h * 64 + d];
    }
}

// ---------------- outer attention: 1 block per (b,h) ----------------
__global__ void outer_attn_kernel()
{
    const int bh = blockIdx.x;         // b*4+h
    const int b  = bh >> 2, h = bh & 3;
    const int tid = threadIdx.x;       // 128

    __shared__ float sq[S_OUT][65], sk[S_OUT][65], sv[S_OUT][65];
    __shared__ float ss[S_OUT][S_OUT];

    for (int i = tid; i < S_OUT * 64; i += blockDim.x) {
        int p = i >> 6, d = i & 63;
        size_t base = (size_t)(b * S_OUT + p) * 768;
        sq[p][d] = g_qkv[base +        h * 64 + d];
        sk[p][d] = g_qkv[base + 256 +  h * 64 + d];
        sv[p][d] = g_qkv[base + 512 +  h * 64 + d];
    }
    __syncthreads();

    for (int i = tid; i < S_OUT * S_OUT; i += blockDim.x) {
        int p = i / S_OUT, j = i % S_OUT;
        float s = 0.f;
        #pragma unroll 16
        for (int c = 0; c < 64; c++) s += sq[p][c] * sk[j][c];
        ss[p][j] = s * 0.125f;
    }
    __syncthreads();

    if (tid < S_OUT) {
        int p = tid;
        float m = -1e30f;
        #pragma unroll
        for (int j = 0; j < S_OUT; j++) m = fmaxf(m, ss[p][j]);
        float sum = 0.f;
        #pragma unroll
        for (int j = 0; j < S_OUT; j++) { float e = __expf(ss[p][j] - m); ss[p][j] = e; sum += e; }
        float inv = 1.f / sum;
        #pragma unroll
        for (int j = 0; j < S_OUT; j++) ss[p][j] *= inv;
    }
    __syncthreads();

    float* op = g_ctxo + (size_t)bh * (S_OUT * 64);
    for (int i = tid; i < S_OUT * 64; i += blockDim.x) {
        int p = i >> 6, c = i & 63;
        float s = 0.f;
        #pragma unroll
        for (int j = 0; j < S_OUT; j++) s += ss[p][j] * sv[j][c];
        op[i] = rnd_tf32(s);
    }
}

// ===== tf32 mma.sync GEMM, 128 x NT block, 8 warps as 2m x 4n (64 x NT/4) =====
// C = act(A[M,K] @ Bt[N,K]^T + bias).  BK=16, 3-stage cp.async ring,
// SINGLE barrier per iteration: at iter i, buffer (i+2)%3 was last read at
// iter i-1 and all warps passed this iter's barrier since, so fill(i+2) is
// safe right after the top sync (no bottom barrier needed).
// k-slot permutation (A/B consistent) -> all fragment loads are LDS.128,
// chunk XOR swizzle c^(row&3) keeps them conflict-free.
// Requires M%128==0, K%4==0, N even.
template<int NT, int ACT, int ROUND>
__global__ void __launch_bounds__(256, 2)
gemm_mma(const float* __restrict__ A, const float* __restrict__ Bt,
         const float* __restrict__ bias, float* __restrict__ C,
         int M, int N, int K)
{
    constexpr int NSUB = NT / 32;          // B n-subtiles per warp (4 or 2)
    __shared__ float As[3][128][16];
    __shared__ float Bs[3][NT][16];

    const int tid  = threadIdx.x;
    const int warp = tid >> 5, lane = tid & 31;
    const int g = lane >> 2, t = lane & 3;
    const int bm = blockIdx.y * 128, bn = blockIdx.x * NT;
    const int wm = (warp & 1) * 64;                 // warp m offset (64 rows)
    const int wn = (warp >> 1) * (NT / 4);          // warp n offset
    const int niter = (K + 15) / 16;

    const uint32_t sA = smem_u32(&As[0][0][0]);
    const uint32_t sB = smem_u32(&Bs[0][0][0]);

    auto fill = [&](int i) {
        const int s = i % 3, k0 = i * 16;
        #pragma unroll
        for (int c2 = tid; c2 < 512; c2 += 256) {      // A: 128 rows x 4 chunks
            int r = c2 >> 2, c = c2 & 3;
            int koff = k0 + c * 4;
            int ok = koff < K;
            cp16(sA + (((s * 128 + r) * 16 + ((c ^ (r & 3)) << 2)) << 2),
                 A + (size_t)(bm + r) * K + (ok ? koff : 0), ok ? 16 : 0);
        }
        #pragma unroll
        for (int c2 = tid; c2 < NT * 4; c2 += 256) {   // B: NT rows x 4 chunks
            int r = c2 >> 2, c = c2 & 3;
            int koff = k0 + c * 4;
            int n = bn + r;
            int ok = (n < N) && (koff < K);
            cp16(sB + (((s * NT + r) * 16 + ((c ^ (r & 3)) << 2)) << 2),
                 Bt + (size_t)(ok ? n : 0) * K + (ok ? koff : 0), ok ? 16 : 0);
        }
        cp_commit();
    };

    float acc[4][NSUB][4] = {};

    fill(0);
    if (niter > 1) fill(1);

    for (int i = 0; i < niter; i++) {
        const int s = i % 3;
        if (i + 1 < niter) cp_wait<1>(); else cp_wait<0>();
        __syncthreads();
        if (i + 2 < niter) fill(i + 2);    // buffer (i+2)%3 free since iter i-1

        float4 alo[4], ahi[4], bf[NSUB];
        #pragma unroll
        for (int mt = 0; mt < 4; mt++) {
            int r0 = wm + mt * 16 + g, r1 = r0 + 8;
            alo[mt] = *reinterpret_cast<const float4*>(&As[s][r0][(t ^ (r0 & 3)) << 2]);
            ahi[mt] = *reinterpret_cast<const float4*>(&As[s][r1][(t ^ (r1 & 3)) << 2]);
        }
        #pragma unroll
        for (int nt = 0; nt < NSUB; nt++) {
            int n = wn + nt * 8 + g;
            bf[nt] = *reinterpret_cast<const float4*>(&Bs[s][n][(t ^ (n & 3)) << 2]);
        }
        #pragma unroll
        for (int mt = 0; mt < 4; mt++)
            #pragma unroll
            for (int nt = 0; nt < NSUB; nt++) {
                mma_tf32(acc[mt][nt],
                         __float_as_uint(alo[mt].x), __float_as_uint(ahi[mt].x),
                         __float_as_uint(alo[mt].y), __float_as_uint(ahi[mt].y),
                         __float_as_uint(bf[nt].x),  __float_as_uint(bf[nt].y));
                mma_tf32(acc[mt][nt],
                         __float_as_uint(alo[mt].z), __float_as_uint(ahi[mt].z),
                         __float_as_uint(alo[mt].w), __float_as_uint(ahi[mt].w),
                         __float_as_uint(bf[nt].z),  __float_as_uint(bf[nt].w));
            }
    }

    // epilogue: acc[mt][nt] -> rows (g, g+8), cols (2t, 2t+1)
    #pragma unroll
    for (int mt = 0; mt < 4; mt++) {
        #pragma unroll
        for (int nt = 0; nt < NSUB; nt++) {
            int row0 = bm + wm + mt * 16 + g;
            int col  = bn + wn + nt * 8 + 2 * t;
            if (col >= N) continue;
            float b0 = bias[col], b1 = bias[col + 1];
            #pragma unroll
            for (int half = 0; half < 2; half++) {
                int r = row0 + half * 8;
                float2 v;
                v.x = acc[mt][nt][half * 2 + 0] + b0;
                v.y = acc[mt][nt][half * 2 + 1] + b1;
                if (ACT)   { v.x = tanh_fast(v.x); v.y = tanh_fast(v.y); }
                if (ROUND) { v.x = rnd_tf32(v.x);  v.y = rnd_tf32(v.y); }
                *reinterpret_cast<float2*>(C + (size_t)r * N + col) = v;
            }
        }
    }
}

static inline int cdiv(int a, int b) { return (a + b - 1) / b; }

extern "C" void kernel_launch(void* const* d_in, const int* in_sizes, int n_in,
                              void* d_out, int out_size)
{
    (void)in_sizes; (void)n_in; (void)out_size;
    const float* x   = (const float*)d_in[0];
    const float* iwq = (const float*)d_in[1];
    const float* ibq = (const float*)d_in[2];
    const float* iwk = (const float*)d_in[3];
    const float* ibk = (const float*)d_in[4];
    const float* iwv = (const float*)d_in[5];
    const float* ibv = (const float*)d_in[6];
    const float* iw1 = (const float*)d_in[7];
    const float* ib1 = (const float*)d_in[8];
    const float* iw2 = (const float*)d_in[9];
    const float* ib2 = (const float*)d_in[10];
    const float* owq = (const float*)d_in[11];
    const float* obq = (const float*)d_in[12];
    const float* owk = (const float*)d_in[13];
    const float* obk = (const float*)d_in[14];
    const float* owv = (const float*)d_in[15];
    const float* obv = (const float*)d_in[16];
    const float* ow1 = (const float*)d_in[17];
    const float* ob1 = (const float*)d_in[18];
    const float* ow2 = (const float*)d_in[19];
    const float* ob2 = (const float*)d_in[20];
    float* out = (float*)d_out;

    float *p_ctx, *p_h1, *p_seq, *p_wpT, *p_bp, *p_qkv, *p_ctxo, *p_h2;
    float *p_w1t, *p_w2t, *p_w3t, *p_w4t;
    cudaGetSymbolAddress((void**)&p_ctx,  g_ctx);
    cudaGetSymbolAddress((void**)&p_h1,   g_h1);
    cudaGetSymbolAddress((void**)&p_seq,  g_seq);
    cudaGetSymbolAddress((void**)&p_wpT,  g_wpackT);
    cudaGetSymbolAddress((void**)&p_bp,   g_bpack);
    cudaGetSymbolAddress((void**)&p_qkv,  g_qkv);
    cudaGetSymbolAddress((void**)&p_ctxo, g_ctxo);
    cudaGetSymbolAddress((void**)&p_h2,   g_h2);
    cudaGetSymbolAddress((void**)&p_w1t,  g_w1t);
    cudaGetSymbolAddress((void**)&p_w2t,  g_w2t);
    cudaGetSymbolAddress((void**)&p_w3t,  g_w3t);
    cudaGetSymbolAddress((void**)&p_w4t,  g_w4t);

    // 0) inner attention -> g_ctx [122880][136] (tf32-rounded)
    inner_attn_kernel<<<NU, 128>>>(x, iwq, ibq, iwk, ibk, iwv, ibv);

    // 1,2) transposes needed for inner GEMMs
    transpose_round<<<dim3(cdiv(256, 32),  cdiv(136, 32)),  dim3(32, 8)>>>(iw1, p_w1t, 136, 256);
    transpose_round<<<dim3(cdiv(64, 32),   cdiv(1024, 32)), dim3(32, 8)>>>(iw2, p_w2t, 1024, 64);

    // 3) fc1_i: [122880,136] @ w1t[256,136]^T + tanh -> g_h1   (ncu capture slot)
    gemm_mma<128, 1, 1><<<dim3(2, FC1I_M / 128), 256>>>(p_ctx, p_w1t, ib1, p_h1, FC1I_M, 256, 136);

    // 4) fc2_i: [30720,1024] @ w2t[64,1024]^T -> g_seq
    gemm_mma<64, 0, 1><<<dim3(1, NU / 128), 256>>>(p_h1, p_w2t, ib2, p_seq, NU, 64, 1024);

    // 5) pack outer qkv (transposed, rounded)
    pack_qkv<<<cdiv(768 * 64, 256), 256>>>(owq, owk, owv, obq, obk, obv);

    // 6) outer qkv: [30720,64] @ wpackT[768,64]^T -> g_qkv
    gemm_mma<128, 0, 0><<<dim3(6, NU / 128), 256>>>(p_seq, p_wpT, p_bp, p_qkv, NU, 768, 64);

    // 7) outer attention -> g_ctxo [4096][1920] (rounded)
    outer_attn_kernel<<<BB * HH, 128>>>();

    // 8,9) transposes for outer GEMMs
    transpose_round<<<dim3(cdiv(1024, 32), cdiv(1920, 32)), dim3(32, 8)>>>(ow1, p_w3t, 1920, 1024);
    transpose_round<<<dim3(cdiv(1080, 32), cdiv(4096, 32)), dim3(32, 8)>>>(ow2, p_w4t, 4096, 1080);

    // 10) fc1_o: [4096,1920] @ w3t[1024,1920]^T + tanh -> g_h2
    gemm_mma<128, 1, 1><<<dim3(8, (BB * HH) / 128), 256>>>(p_ctxo, p_w3t, ob1, p_h2, BB * HH, 1024, 1920);

    // 11) fc2_o: [1024,4096] @ w4t[1080,4096]^T -> out
    gemm_mma<128, 0, 0><<<dim3(cdiv(OUT_O, 128), BB / 128), 256>>>(p_h2, p_w4t, ob2, out, BB, OUT_O, HH * HID_O);
}

// round 8
// speedup vs baseline: 2.9996x; 1.1564x over previous
#include <cuda_runtime.h>
#include <cuda_bf16.h>
#include <cstdint>

// ---------------- problem constants ----------------
#define BB      1024
#define S_OUT   30
#define S_IN    17
#define D_INN   3
#define HH      4
#define DKQ_I   6
#define DV_I    8
#define HID_I   256
#define OUT_I   64
#define HID_O   1024
#define OUT_O   1080

#define NU      (BB * S_OUT)          // 30720 inner units
#define CTXI_PER_U (HH * S_IN * DV_I) // 544
#define FC1I_M  (NU * HH)             // 122880
#define FC1I_K  (S_IN * DV_I)         // 136

// ---------------- scratch (device globals; no runtime allocation) -------------
__device__ float g_ctx  [(size_t)NU * CTXI_PER_U + 64];   // [122880][136]
__device__ float g_h1   [(size_t)FC1I_M * HID_I];         // [30720][1024]
__device__ float g_seq  [(size_t)NU * 64];                // [30720][64]
__device__ float g_wpackT[768 * 64];                      // [n=768][k=64] rounded
__device__ float g_bpack[768];
__device__ float g_qkv  [(size_t)NU * 768];               // [30720][768]
__device__ float g_ctxo [(size_t)BB * HH * S_OUT * 64];   // [4096][1920]
__device__ float g_h2   [(size_t)BB * HH * HID_O];        // [1024][4096]
__device__ float g_part [(size_t)4 * BB * OUT_O];         // split-K partials fc2_o
// transposed + tf32-rounded weights ([N][K])
__device__ float g_w1t[256 * 136];
__device__ float g_w2t[64 * 1024];
__device__ float g_w3t[1024 * 1920];
__device__ float g_w4t[1080 * 4096];

// ---------------- helpers ----------------
__device__ __forceinline__ float tanh_fast(float x) {
    float y; asm("tanh.approx.f32 %0, %1;" : "=f"(y) : "f"(x)); return y;
}
// round fp32 -> tf32 precision (RNA when followed by HW truncation of low 13 bits)
__device__ __forceinline__ float rnd_tf32(float f) {
    return __uint_as_float(__float_as_uint(f) + 0x1000u);
}
__device__ __forceinline__ uint32_t smem_u32(const void* p) {
    uint32_t a;
    asm("{ .reg .u64 t; cvta.to.shared.u64 t, %1; cvt.u32.u64 %0, t; }" : "=r"(a) : "l"(p));
    return a;
}
__device__ __forceinline__ void cp16(uint32_t dst, const void* src, int sz) {
    asm volatile("cp.async.cg.shared.global [%0], [%1], 16, %2;"
                 :: "r"(dst), "l"(src), "r"(sz) : "memory");
}
__device__ __forceinline__ void cp_commit() {
    asm volatile("cp.async.commit_group;" ::: "memory");
}
template<int N> __device__ __forceinline__ void cp_wait() {
    asm volatile("cp.async.wait_group %0;" :: "n"(N) : "memory");
}
__device__ __forceinline__ void mma_tf32(float c[4], uint32_t a0, uint32_t a1,
                                         uint32_t a2, uint32_t a3,
                                         uint32_t b0, uint32_t b1) {
    asm volatile(
        "mma.sync.aligned.m16n8k8.row.col.f32.tf32.tf32.f32 "
        "{%0,%1,%2,%3}, {%4,%5,%6,%7}, {%8,%9}, {%0,%1,%2,%3};"
        : "+f"(c[0]), "+f"(c[1]), "+f"(c[2]), "+f"(c[3])
        : "r"(a0), "r"(a1), "r"(a2), "r"(a3), "r"(b0), "r"(b1));
}

// ---------------- inner attention: 1 block per (b,s_out), 1 warp per head -----
__global__ void inner_attn_kernel(const float* __restrict__ x,
                                  const float* __restrict__ iwq, const float* __restrict__ ibq,
                                  const float* __restrict__ iwk, const float* __restrict__ ibk,
                                  const float* __restrict__ iwv, const float* __restrict__ ibv)
{
    const int u    = blockIdx.x;
    const int tid  = threadIdx.x;
    const int h    = tid >> 5;
    const int lane = tid & 31;

    __shared__ float sx[S_IN * D_INN];
    __shared__ float sq[HH][S_IN][DKQ_I];
    __shared__ float sk[HH][S_IN][DKQ_I];
    __shared__ float sv[HH][S_IN][DV_I];
    __shared__ float ss[HH][S_IN][S_IN];

    const float* xp = x + (size_t)u * (S_IN * D_INN);
    if (tid < S_IN * D_INN) sx[tid] = xp[tid];
    __syncthreads();

    for (int i = lane; i < S_IN * (2 * DKQ_I + DV_I); i += 32) {
        if (i < S_IN * DKQ_I) {
            int p = i / DKQ_I, c = i % DKQ_I;
            float s = ibq[h * DKQ_I + c];
            #pragma unroll
            for (int d = 0; d < D_INN; d++)
                s += sx[p * D_INN + d] * iwq[(h * D_INN + d) * DKQ_I + c];
            sq[h][p][c] = s;
        } else if (i < 2 * S_IN * DKQ_I) {
            int j = i - S_IN * DKQ_I;
            int p = j / DKQ_I, c = j % DKQ_I;
            float s = ibk[h * DKQ_I + c];
            #pragma unroll
            for (int d = 0; d < D_INN; d++)
                s += sx[p * D_INN + d] * iwk[(h * D_INN + d) * DKQ_I + c];
            sk[h][p][c] = s;
        } else {
            int j = i - 2 * S_IN * DKQ_I;
            int p = j / DV_I, c = j % DV_I;
            float s = ibv[h * DV_I + c];
            #pragma unroll
            for (int d = 0; d < D_INN; d++)
                s += sx[p * D_INN + d] * iwv[(h * D_INN + d) * DV_I + c];
            sv[h][p][c] = s;
        }
    }
    __syncwarp();

    const float scale = 0.40824829046386302f;   // 1/sqrt(6)
    for (int i = lane; i < S_IN * S_IN; i += 32) {
        int p = i / S_IN, j = i % S_IN;
        float s = 0.f;
        #pragma unroll
        for (int c = 0; c < DKQ_I; c++) s += sq[h][p][c] * sk[h][j][c];
        ss[h][p][j] = s * scale;
    }
    __syncwarp();

    if (lane < S_IN) {
        int p = lane;
        float m = -1e30f;
        #pragma unroll
        for (int j = 0; j < S_IN; j++) m = fmaxf(m, ss[h][p][j]);
        float sum = 0.f;
        #pragma unroll
        for (int j = 0; j < S_IN; j++) { float e = __expf(ss[h][p][j] - m); ss[h][p][j] = e; sum += e; }
        float inv = 1.f / sum;
        #pragma unroll
        for (int j = 0; j < S_IN; j++) ss[h][p][j] *= inv;
    }
    __syncwarp();

    float* op = g_ctx + (size_t)u * CTXI_PER_U + h * (S_IN * DV_I);
    for (int i = lane; i < S_IN * DV_I; i += 32) {
        int p = i / DV_I, c = i % DV_I;
        float s = 0.f;
        #pragma unroll
        for (int j = 0; j < S_IN; j++) s += ss[h][p][j] * sv[h][j][c];
        op[p * DV_I + c] = rnd_tf32(s);      // GEMM A-side input: tf32-rounded
    }
}

// ---------------- weight transpose + tf32 round: W[K][N] -> Wt[N][K] ----------
__global__ void transpose_round(const float* __restrict__ W, float* __restrict__ Wt,
                                int K, int N)
{
    __shared__ float t[32][33];
    int kb = blockIdx.y * 32, nb = blockIdx.x * 32;
    int x = threadIdx.x, y = threadIdx.y;   // 32 x 8
    #pragma unroll
    for (int dy = 0; dy < 32; dy += 8) {
        int k = kb + y + dy, n = nb + x;
        t[y + dy][x] = (k < K && n < N) ? W[(size_t)k * N + n] : 0.f;
    }
    __syncthreads();
    #pragma unroll
    for (int dy = 0; dy < 32; dy += 8) {
        int n = nb + y + dy, k = kb + x;
        if (n < N && k < K) Wt[(size_t)n * K + k] = rnd_tf32(t[x][y + dy]);
    }
}

// ---------------- pack outer qkv weights transposed [768][64] + bias ----------
__global__ void pack_qkv(const float* __restrict__ owq, const float* __restrict__ owk,
                         const float* __restrict__ owv,
                         const float* __restrict__ obq, const float* __restrict__ obk,
                         const float* __restrict__ obv)
{
    int i = blockIdx.x * blockDim.x + threadIdx.x;
    if (i < 768 * 64) {
        int col = i / 64, k = i % 64;
        int sel = col >> 8, hd = col & 255;
        int h = hd >> 6, d = hd & 63;
        const float* w = (sel == 0) ? owq : (sel == 1) ? owk : owv;
        g_wpackT[i] = rnd_tf32(w[(h * 64 + k) * 64 + d]);
    }
    if (i < 768) {
        int sel = i >> 8, hd = i & 255;
        int h = hd >> 6, d = hd & 63;
        const float* b = (sel == 0) ? obq : (sel == 1) ? obk : obv;
        g_bpack[i] = b[h * 64 + d];
    }
}

// ---------------- outer attention: 1 block per (b,h) ----------------
__global__ void outer_attn_kernel()
{
    const int bh = blockIdx.x;         // b*4+h
    const int b  = bh >> 2, h = bh & 3;
    const int tid = threadIdx.x;       // 128

    __shared__ float sq[S_OUT][65], sk[S_OUT][65], sv[S_OUT][65];
    __shared__ float ss[S_OUT][S_OUT];

    for (int i = tid; i < S_OUT * 64; i += blockDim.x) {
        int p = i >> 6, d = i & 63;
        size_t base = (size_t)(b * S_OUT + p) * 768;
        sq[p][d] = g_qkv[base +        h * 64 + d];
        sk[p][d] = g_qkv[base + 256 +  h * 64 + d];
        sv[p][d] = g_qkv[base + 512 +  h * 64 + d];
    }
    __syncthreads();

    for (int i = tid; i < S_OUT * S_OUT; i += blockDim.x) {
        int p = i / S_OUT, j = i % S_OUT;
        float s = 0.f;
        #pragma unroll 16
        for (int c = 0; c < 64; c++) s += sq[p][c] * sk[j][c];
        ss[p][j] = s * 0.125f;
    }
    __syncthreads();

    if (tid < S_OUT) {
        int p = tid;
        float m = -1e30f;
        #pragma unroll
        for (int j = 0; j < S_OUT; j++) m = fmaxf(m, ss[p][j]);
        float sum = 0.f;
        #pragma unroll
        for (int j = 0; j < S_OUT; j++) { float e = __expf(ss[p][j] - m); ss[p][j] = e; sum += e; }
        float inv = 1.f / sum;
        #pragma unroll
        for (int j = 0; j < S_OUT; j++) ss[p][j] *= inv;
    }
    __syncthreads();

    float* op = g_ctxo + (size_t)bh * (S_OUT * 64);
    for (int i = tid; i < S_OUT * 64; i += blockDim.x) {
        int p = i >> 6, c = i & 63;
        float s = 0.f;
        #pragma unroll
        for (int j = 0; j < S_OUT; j++) s += ss[p][j] * sv[j][c];
        op[i] = rnd_tf32(s);
    }
}

// ===== tf32 mma.sync GEMM, 128 x NT block, 8 warps as 2m x 4n (64 x NT/4) =====
// C = act(A[M,K] @ Bt[N,K]^T + bias).  BK=16, 3-stage cp.async ring, single
// barrier per iteration.  k-slot permutation -> all fragment loads LDS.128,
// chunk XOR swizzle c^(row&3) conflict-free.
// Split-K: gridDim.z slices of k_slice; PART=1 stores raw partials to
// C + z*M*N (no bias/act).  Requires M%128==0, K%4==0, N even, k_slice%16==0.
template<int NT, int ACT, int ROUND, int PART>
__global__ void __launch_bounds__(256, 2)
gemm_mma(const float* __restrict__ A, const float* __restrict__ Bt,
         const float* __restrict__ bias, float* __restrict__ C,
         int M, int N, int K, int k_slice)
{
    constexpr int NSUB = NT / 32;          // B n-subtiles per warp (4 or 2)
    __shared__ float As[3][128][16];
    __shared__ float Bs[3][NT][16];

    const int tid  = threadIdx.x;
    const int warp = tid >> 5, lane = tid & 31;
    const int g = lane >> 2, t = lane & 3;
    const int bm = blockIdx.y * 128, bn = blockIdx.x * NT;
    const int wm = (warp & 1) * 64;                 // warp m offset (64 rows)
    const int wn = (warp >> 1) * (NT / 4);          // warp n offset
    const int kb = blockIdx.z * k_slice;
    const int kend = min(kb + k_slice, K);
    const int niter = (kend - kb + 15) / 16;

    const uint32_t sA = smem_u32(&As[0][0][0]);
    const uint32_t sB = smem_u32(&Bs[0][0][0]);

    auto fill = [&](int i) {
        const int s = i % 3, k0 = kb + i * 16;
        #pragma unroll
        for (int c2 = tid; c2 < 512; c2 += 256) {      // A: 128 rows x 4 chunks
            int r = c2 >> 2, c = c2 & 3;
            int koff = k0 + c * 4;
            int ok = koff < kend;
            cp16(sA + (((s * 128 + r) * 16 + ((c ^ (r & 3)) << 2)) << 2),
                 A + (size_t)(bm + r) * K + (ok ? koff : 0), ok ? 16 : 0);
        }
        #pragma unroll
        for (int c2 = tid; c2 < NT * 4; c2 += 256) {   // B: NT rows x 4 chunks
            int r = c2 >> 2, c = c2 & 3;
            int koff = k0 + c * 4;
            int n = bn + r;
            int ok = (n < N) && (koff < kend);
            cp16(sB + (((s * NT + r) * 16 + ((c ^ (r & 3)) << 2)) << 2),
                 Bt + (size_t)(ok ? n : 0) * K + (ok ? koff : 0), ok ? 16 : 0);
        }
        cp_commit();
    };

    float acc[4][NSUB][4] = {};

    fill(0);
    if (niter > 1) fill(1);

    for (int i = 0; i < niter; i++) {
        const int s = i % 3;
        if (i + 1 < niter) cp_wait<1>(); else cp_wait<0>();
        __syncthreads();
        if (i + 2 < niter) fill(i + 2);    // buffer (i+2)%3 free since iter i-1

        float4 alo[4], ahi[4], bf[NSUB];
        #pragma unroll
        for (int mt = 0; mt < 4; mt++) {
            int r0 = wm + mt * 16 + g, r1 = r0 + 8;
            alo[mt] = *reinterpret_cast<const float4*>(&As[s][r0][(t ^ (r0 & 3)) << 2]);
            ahi[mt] = *reinterpret_cast<const float4*>(&As[s][r1][(t ^ (r1 & 3)) << 2]);
        }
        #pragma unroll
        for (int nt = 0; nt < NSUB; nt++) {
            int n = wn + nt * 8 + g;
            bf[nt] = *reinterpret_cast<const float4*>(&Bs[s][n][(t ^ (n & 3)) << 2]);
        }
        #pragma unroll
        for (int mt = 0; mt < 4; mt++)
            #pragma unroll
            for (int nt = 0; nt < NSUB; nt++) {
                mma_tf32(acc[mt][nt],
                         __float_as_uint(alo[mt].x), __float_as_uint(ahi[mt].x),
                         __float_as_uint(alo[mt].y), __float_as_uint(ahi[mt].y),
                         __float_as_uint(bf[nt].x),  __float_as_uint(bf[nt].y));
                mma_tf32(acc[mt][nt],
                         __float_as_uint(alo[mt].z), __float_as_uint(ahi[mt].z),
                         __float_as_uint(alo[mt].w), __float_as_uint(ahi[mt].w),
                         __float_as_uint(bf[nt].z),  __float_as_uint(bf[nt].w));
            }
    }

    // epilogue: acc[mt][nt] -> rows (g, g+8), cols (2t, 2t+1)
    float* Cz = PART ? (C + (size_t)blockIdx.z * M * N) : C;
    #pragma unroll
    for (int mt = 0; mt < 4; mt++) {
        #pragma unroll
        for (int nt = 0; nt < NSUB; nt++) {
            int row0 = bm + wm + mt * 16 + g;
            int col  = bn + wn + nt * 8 + 2 * t;
            if (col >= N) continue;
            float b0 = PART ? 0.f : bias[col];
            float b1 = PART ? 0.f : bias[col + 1];
            #pragma unroll
            for (int half = 0; half < 2; half++) {
                int r = row0 + half * 8;
                float2 v;
                v.x = acc[mt][nt][half * 2 + 0] + b0;
                v.y = acc[mt][nt][half * 2 + 1] + b1;
                if (!PART && ACT)   { v.x = tanh_fast(v.x); v.y = tanh_fast(v.y); }
                if (!PART && ROUND) { v.x = rnd_tf32(v.x);  v.y = rnd_tf32(v.y); }
                *reinterpret_cast<float2*>(Cz + (size_t)r * N + col) = v;
            }
        }
    }
}

// ---------------- split-K reduce: out = sum_s part[s] + bias ------------------
template<int S>
__global__ void reduce_splitk(const float* __restrict__ part, const float* __restrict__ bias,
                              float* __restrict__ out, int M, int N)
{
    int idx = blockIdx.x * blockDim.x + threadIdx.x;
    if (idx >= M * N) return;
    int n = idx % N;
    float s = bias[n];
    #pragma unroll
    for (int i = 0; i < S; i++) s += part[(size_t)i * M * N + idx];
    out[idx] = s;
}

static inline int cdiv(int a, int b) { return (a + b - 1) / b; }

extern "C" void kernel_launch(void* const* d_in, const int* in_sizes, int n_in,
                              void* d_out, int out_size)
{
    (void)in_sizes; (void)n_in; (void)out_size;
    const float* x   = (const float*)d_in[0];
    const float* iwq = (const float*)d_in[1];
    const float* ibq = (const float*)d_in[2];
    const float* iwk = (const float*)d_in[3];
    const float* ibk = (const float*)d_in[4];
    const float* iwv = (const float*)d_in[5];
    const float* ibv = (const float*)d_in[6];
    const float* iw1 = (const float*)d_in[7];
    const float* ib1 = (const float*)d_in[8];
    const float* iw2 = (const float*)d_in[9];
    const float* ib2 = (const float*)d_in[10];
    const float* owq = (const float*)d_in[11];
    const float* obq = (const float*)d_in[12];
    const float* owk = (const float*)d_in[13];
    const float* obk = (const float*)d_in[14];
    const float* owv = (const float*)d_in[15];
    const float* obv = (const float*)d_in[16];
    const float* ow1 = (const float*)d_in[17];
    const float* ob1 = (const float*)d_in[18];
    const float* ow2 = (const float*)d_in[19];
    const float* ob2 = (const float*)d_in[20];
    float* out = (float*)d_out;

    float *p_ctx, *p_h1, *p_seq, *p_wpT, *p_bp, *p_qkv, *p_ctxo, *p_h2, *p_part;
    float *p_w1t, *p_w2t, *p_w3t, *p_w4t;
    cudaGetSymbolAddress((void**)&p_ctx,  g_ctx);
    cudaGetSymbolAddress((void**)&p_h1,   g_h1);
    cudaGetSymbolAddress((void**)&p_seq,  g_seq);
    cudaGetSymbolAddress((void**)&p_wpT,  g_wpackT);
    cudaGetSymbolAddress((void**)&p_bp,   g_bpack);
    cudaGetSymbolAddress((void**)&p_qkv,  g_qkv);
    cudaGetSymbolAddress((void**)&p_ctxo, g_ctxo);
    cudaGetSymbolAddress((void**)&p_h2,   g_h2);
    cudaGetSymbolAddress((void**)&p_part, g_part);
    cudaGetSymbolAddress((void**)&p_w1t,  g_w1t);
    cudaGetSymbolAddress((void**)&p_w2t,  g_w2t);
    cudaGetSymbolAddress((void**)&p_w3t,  g_w3t);
    cudaGetSymbolAddress((void**)&p_w4t,  g_w4t);

    // 0) inner attention -> g_ctx [122880][136] (tf32-rounded)
    inner_attn_kernel<<<NU, 128>>>(x, iwq, ibq, iwk, ibk, iwv, ibv);

    // 1,2) transposes needed for inner GEMMs
    transpose_round<<<dim3(cdiv(256, 32),  cdiv(136, 32)),  dim3(32, 8)>>>(iw1, p_w1t, 136, 256);
    transpose_round<<<dim3(cdiv(64, 32),   cdiv(1024, 32)), dim3(32, 8)>>>(iw2, p_w2t, 1024, 64);

    // 3) fc1_i: [122880,136] @ w1t[256,136]^T + tanh -> g_h1   (ncu capture slot)
    gemm_mma<128, 1, 1, 0><<<dim3(2, FC1I_M / 128), 256>>>(
        p_ctx, p_w1t, ib1, p_h1, FC1I_M, 256, 136, 136);

    // 4) fc2_i: [30720,1024] @ w2t[64,1024]^T -> g_seq
    gemm_mma<64, 0, 1, 0><<<dim3(1, NU / 128), 256>>>(
        p_h1, p_w2t, ib2, p_seq, NU, 64, 1024, 1024);

    // 5) pack outer qkv (transposed, rounded)
    pack_qkv<<<cdiv(768 * 64, 256), 256>>>(owq, owk, owv, obq, obk, obv);

    // 6) outer qkv: [30720,64] @ wpackT[768,64]^T -> g_qkv
    gemm_mma<128, 0, 0, 0><<<dim3(6, NU / 128), 256>>>(
        p_seq, p_wpT, p_bp, p_qkv, NU, 768, 64, 64);

    // 7) outer attention -> g_ctxo [4096][1920] (rounded)
    outer_attn_kernel<<<BB * HH, 128>>>();

    // 8,9) transposes for outer GEMMs
    transpose_round<<<dim3(cdiv(1024, 32), cdiv(1920, 32)), dim3(32, 8)>>>(ow1, p_w3t, 1920, 1024);
    transpose_round<<<dim3(cdiv(1080, 32), cdiv(4096, 32)), dim3(32, 8)>>>(ow2, p_w4t, 4096, 1080);

    // 10) fc1_o: [4096,1920] @ w3t[1024,1920]^T + tanh -> g_h2  (256 CTAs = 1 wave)
    gemm_mma<128, 1, 1, 0><<<dim3(8, (BB * HH) / 128), 256>>>(
        p_ctxo, p_w3t, ob1, p_h2, BB * HH, 1024, 1920, 1920);

    // 11) fc2_o split-K=4: [1024,4096] @ w4t[1080,4096]^T -> partials (288 CTAs = 1 wave)
    gemm_mma<128, 0, 0, 1><<<dim3(cdiv(OUT_O, 128), BB / 128, 4), 256>>>(
        p_h2, p_w4t, nullptr, p_part, BB, OUT_O, HH * HID_O, 1024);

    // 12) reduce partials + bias -> out
    reduce_splitk<4><<<cdiv(BB * OUT_O, 256), 256>>>(p_part, ob2, out, BB, OUT_O);
}